// round 1
// baseline (speedup 1.0000x reference)
#include <cuda_runtime.h>
#include <math.h>
#include <float.h>

#define NPTS 80000
#define CH   64
#define KN   27
#define NB   2
#define NXX  3
#define CAQ  192   // CH*NXX
#define HID  12    // CAQ/RED

// ---------------- scratch (device globals; no allocation allowed) ----------
__device__ float g_bufA[NPTS*CH];
__device__ float g_bufB[NPTS*CH];
__device__ float g_kx0[NPTS*CH];
__device__ float g_kx1[NPTS*CH];
__device__ float g_kx2[NPTS*CH];
__device__ float g_sum[CH];
__device__ float g_sumsq[CH];
__device__ float g_segsum[NB*CAQ];
__device__ float g_segmax[NB*CAQ];
__device__ float g_att[NB*CAQ];
__device__ float g_wsig[NXX];

// ---------------- packed fp32x2 helpers (Blackwell FFMA2 path) -------------
__device__ __forceinline__ unsigned long long dup2(float x){
  unsigned long long r; asm("mov.b64 %0, {%1, %1};" : "=l"(r) : "f"(x)); return r;
}
__device__ __forceinline__ void fma2(unsigned long long &d, unsigned long long a, unsigned long long b){
  asm("fma.rn.f32x2 %0, %1, %2, %0;" : "+l"(d) : "l"(a), "l"(b));
}
__device__ __forceinline__ float2 unpack2(unsigned long long u){
  float2 f; asm("mov.b64 {%0, %1}, %2;" : "=f"(f.x), "=f"(f.y) : "l"(u)); return f;
}

__device__ __forceinline__ void atomicMaxFloat(float* addr, float val){
  int* ai = (int*)addr;
  int old = *ai;
  while (true){
    float fo = __int_as_float(old);
    if (fo >= val) break;
    int assumed = old;
    old = atomicCAS(ai, assumed, __float_as_int(val));
    if (old == assumed) break;
  }
}

// ---------------- gathered GEMM: dst = sum_k gather_k(src) @ W[k] ----------
// tile: 128 rows x 64 cols, 256 threads, per-thread 8 rows x 4 cols
// accumulators packed as f32x2 over row pairs -> 16 FFMA2 per kk step
__global__ void __launch_bounds__(256, 2) conv_kernel(
    const float* __restrict__ src, const int* __restrict__ nbr,
    const float* __restrict__ W, float* __restrict__ dst)
{
  __shared__ float As[CH][128];   // [kk][row]  32 KB (transposed gathered tile)
  __shared__ float Ws[CH][CH];    // [kk][col]  16 KB
  const int tid  = threadIdx.x;
  const int row0 = blockIdx.x * 128;
  const int tx = tid & 15;        // col group: cols tx*4 .. tx*4+3
  const int ty = tid >> 4;        // row group: rows ty*8 .. ty*8+7
  const int lr = tid & 127;       // gather row
  const int cb = (tid >> 7) * 32; // gather col half

  unsigned long long acc[4][4];
#pragma unroll
  for (int i=0;i<4;i++)
#pragma unroll
    for (int j=0;j<4;j++) acc[i][j]=0ULL;

  for (int k=0;k<KN;k++){
    __syncthreads();
    // stage W[k] (64x64)
    const float4* wg  = (const float4*)(W + k*CH*CH);
    float4*       wsv = (float4*)(&Ws[0][0]);
#pragma unroll
    for (int i=0;i<4;i++) wsv[tid + 256*i] = wg[tid + 256*i];

    // gather A tile (transposed into As[kk][row])
    int idx = __ldg(&nbr[(row0+lr)*KN + k]);
    if (idx >= 0){
      const float4* xg = (const float4*)(src + (size_t)idx*CH + cb);
#pragma unroll
      for (int j=0;j<8;j++){
        float4 v = xg[j];
        int c = cb + j*4;
        As[c][lr]=v.x; As[c+1][lr]=v.y; As[c+2][lr]=v.z; As[c+3][lr]=v.w;
      }
    } else {
#pragma unroll
      for (int j=0;j<8;j++){
        int c = cb + j*4;
        As[c][lr]=0.f; As[c+1][lr]=0.f; As[c+2][lr]=0.f; As[c+3][lr]=0.f;
      }
    }
    __syncthreads();

#pragma unroll 8
    for (int kk=0;kk<CH;kk++){
      const ulonglong2* ap = (const ulonglong2*)(&As[kk][ty*8]);
      ulonglong2 av0 = ap[0];
      ulonglong2 av1 = ap[1];
      float4 bv = *(const float4*)(&Ws[kk][tx*4]);
      unsigned long long b0=dup2(bv.x), b1=dup2(bv.y), b2=dup2(bv.z), b3=dup2(bv.w);
      fma2(acc[0][0],av0.x,b0); fma2(acc[0][1],av0.x,b1); fma2(acc[0][2],av0.x,b2); fma2(acc[0][3],av0.x,b3);
      fma2(acc[1][0],av0.y,b0); fma2(acc[1][1],av0.y,b1); fma2(acc[1][2],av0.y,b2); fma2(acc[1][3],av0.y,b3);
      fma2(acc[2][0],av1.x,b0); fma2(acc[2][1],av1.x,b1); fma2(acc[2][2],av1.x,b2); fma2(acc[2][3],av1.x,b3);
      fma2(acc[3][0],av1.y,b0); fma2(acc[3][1],av1.y,b1); fma2(acc[3][2],av1.y,b2); fma2(acc[3][3],av1.y,b3);
    }
  }

#pragma unroll
  for (int rp=0;rp<4;rp++){
    float2 f0=unpack2(acc[rp][0]), f1=unpack2(acc[rp][1]);
    float2 f2=unpack2(acc[rp][2]), f3=unpack2(acc[rp][3]);
    int r = row0 + ty*8 + rp*2;
    float4 lo4 = make_float4(f0.x,f1.x,f2.x,f3.x);
    float4 hi4 = make_float4(f0.y,f1.y,f2.y,f3.y);
    *(float4*)(&dst[(size_t)r*CH + tx*4])     = lo4;
    *(float4*)(&dst[(size_t)(r+1)*CH + tx*4]) = hi4;
  }
}

// ---------------- per-channel sum / sumsq over N --------------------------
__global__ void clear_stats_kernel(){
  int t=threadIdx.x; if (t<CH){ g_sum[t]=0.f; g_sumsq[t]=0.f; }
}
__global__ void stats_kernel(const float* __restrict__ x){
  __shared__ float ss[256], qq[256];
  int c  = threadIdx.x & 63;
  int rl = blockIdx.x*4 + (threadIdx.x>>6);   // 512 row lanes
  float s=0.f, q=0.f;
  for (int n=rl; n<NPTS; n+=512){
    float v = x[n*CH + c];
    s += v; q += v*v;
  }
  ss[threadIdx.x]=s; qq[threadIdx.x]=q;
  __syncthreads();
  if (threadIdx.x<64){
    s = ss[threadIdx.x]+ss[threadIdx.x+64]+ss[threadIdx.x+128]+ss[threadIdx.x+192];
    q = qq[threadIdx.x]+qq[threadIdx.x+64]+qq[threadIdx.x+128]+qq[threadIdx.x+192];
    atomicAdd(&g_sum[c], s);
    atomicAdd(&g_sumsq[c], q);
  }
}

// ---------------- BN apply (in place), optional relu -----------------------
__global__ void bn_kernel(float* __restrict__ x, const float* __restrict__ gg,
                          const float* __restrict__ bb, int relu){
  __shared__ float sc[64], bi[64];
  int t = threadIdx.x;
  if (t<64){
    float m = g_sum[t]*(1.f/NPTS);
    float v = g_sumsq[t]*(1.f/NPTS) - m*m;
    float s = rsqrtf(v + 1e-5f) * gg[t];
    sc[t]=s; bi[t]=bb[t]-m*s;
  }
  __syncthreads();
  int i4 = blockIdx.x*256 + t;
  float4* xp = (float4*)x;
  float4 v = xp[i4];
  int c = (i4 & 15)*4;
  v.x = v.x*sc[c]+bi[c];   v.y = v.y*sc[c+1]+bi[c+1];
  v.z = v.z*sc[c+2]+bi[c+2]; v.w = v.w*sc[c+3]+bi[c+3];
  if (relu){ v.x=fmaxf(v.x,0.f); v.y=fmaxf(v.y,0.f); v.z=fmaxf(v.z,0.f); v.w=fmaxf(v.w,0.f); }
  xp[i4] = v;
}

// ---------------- segment sum/max over batches (B=2), 192 channels ---------
__global__ void clear_seg_kernel(){
  int t=threadIdx.x; if (t<NB*CAQ){ g_segsum[t]=0.f; g_segmax[t]=-FLT_MAX; }
}
__global__ void seg_kernel(const int* __restrict__ bidx){
  int j = threadIdx.x;                      // 0..191 (channel of xcat)
  const float* kxp = (j<64)? g_kx0 : ((j<128)? g_kx1 : g_kx2);
  int c = j & 63;
  int n0 = blockIdx.x*400, n1 = n0+400;
  float s0=0.f, s1=0.f, m0=-FLT_MAX, m1=-FLT_MAX;
  for (int n=n0;n<n1;n++){
    float v = kxp[n*CH + c];
    if (bidx[n]==0){ s0+=v; m0=fmaxf(m0,v); } else { s1+=v; m1=fmaxf(m1,v); }
  }
  atomicAdd(&g_segsum[j], s0);
  atomicAdd(&g_segsum[CAQ+j], s1);
  atomicMaxFloat(&g_segmax[j], m0);
  atomicMaxFloat(&g_segmax[CAQ+j], m1);
}

// ---------------- tiny FC + sigmoid attention ------------------------------
__global__ void fc_kernel(const int* __restrict__ bidx,
    const float* __restrict__ w1, const float* __restrict__ b1,
    const float* __restrict__ w2, const float* __restrict__ b2,
    const float* __restrict__ ksw)
{
  __shared__ float ha[NB][HID], hm[NB][HID];
  __shared__ int red[256];
  __shared__ int scnt[NB];
  int t = threadIdx.x;
  int c0 = 0;
  for (int n=t; n<NPTS; n+=256) c0 += (bidx[n]==0);
  red[t]=c0; __syncthreads();
  for (int s=128;s>0;s>>=1){ if (t<s) red[t]+=red[t+s]; __syncthreads(); }
  if (t==0){ scnt[0]=red[0]; scnt[1]=NPTS-red[0]; }
  __syncthreads();
  if (t<48){
    int which = t/24;          // 0=avg, 1=max
    int b  = (t/12)%2;
    int tt = t%12;
    float s = b1[tt];
    float inv = 1.f/(float)scnt[b];
    for (int j=0;j<CAQ;j++){
      float z = which ? g_segmax[b*CAQ+j] : g_segsum[b*CAQ+j]*inv;
      s += z * w1[j*HID+tt];
    }
    s = fmaxf(s,0.f);
    if (which) hm[b][tt]=s; else ha[b][tt]=s;
  }
  __syncthreads();
  for (int o=t; o<NB*CAQ; o+=256){
    int b=o/CAQ, j=o%CAQ;
    float sa=b2[j], sm=b2[j];
    for (int tt=0;tt<HID;tt++){ sa += ha[b][tt]*w2[tt*CAQ+j]; sm += hm[b][tt]*w2[tt*CAQ+j]; }
    float s = sa+sm;
    g_att[o] = 1.f/(1.f+expf(-s));
  }
  if (t<NXX) g_wsig[t] = 1.f/(1.f+expf(-ksw[t]));
}

// ---------------- fusion epilogue ------------------------------------------
__device__ __forceinline__ float kx_read(int sel, int off){
  return sel==0 ? g_kx0[off] : (sel==1 ? g_kx1[off] : g_kx2[off]);
}
__global__ void final_kernel(const float* __restrict__ feats,
                             const int* __restrict__ bidx,
                             float* __restrict__ out){
  int i = blockIdx.x*256 + threadIdx.x;
  int n = i >> 6, c = i & 63;
  int b = bidx[n];
  float acc = feats[i];
#pragma unroll
  for (int ii=0; ii<NXX; ii++){
    int j = 3*c + ii;                 // reshape(N,C,NX) crosses kx blocks
    int sel = j >> 6, col = j & 63;
    float xj  = kx_read(sel, n*CH + col);
    float kxi = kx_read(ii, i);
    acc += g_wsig[ii] * (kxi + xj * g_att[b*CAQ + j]);
  }
  out[i] = fmaxf(acc, 0.f);
}

// ---------------- launch ----------------------------------------------------
extern "C" void kernel_launch(void* const* d_in, const int* in_sizes, int n_in,
                              void* d_out, int out_size){
  (void)in_sizes; (void)n_in; (void)out_size;
  const float* feats=(const float*)d_in[0];
  const int*   bidx =(const int*)d_in[1];
  const int*   nbr  =(const int*)d_in[2];
  const float* W1 =(const float*)d_in[3];
  const float* g1 =(const float*)d_in[4];
  const float* b1 =(const float*)d_in[5];
  const float* W2 =(const float*)d_in[6];
  const float* g2 =(const float*)d_in[7];
  const float* b2 =(const float*)d_in[8];
  const float* Wk =(const float*)d_in[9];
  const float* gk =(const float*)d_in[10];
  const float* bk =(const float*)d_in[11];
  const float* fc1w=(const float*)d_in[12];
  const float* fc1b=(const float*)d_in[13];
  const float* fc2w=(const float*)d_in[14];
  const float* fc2b=(const float*)d_in[15];
  const float* ksw =(const float*)d_in[16];
  float* out=(float*)d_out;

  float *pA,*pB,*pk0,*pk1,*pk2;
  cudaGetSymbolAddress((void**)&pA,  g_bufA);
  cudaGetSymbolAddress((void**)&pB,  g_bufB);
  cudaGetSymbolAddress((void**)&pk0, g_kx0);
  cudaGetSymbolAddress((void**)&pk1, g_kx1);
  cudaGetSymbolAddress((void**)&pk2, g_kx2);

  struct Step { const float* src; const float* W; float* dst;
                const float* g; const float* b; int relu; };
  Step steps[5] = {
    {feats, W1,                 pA,  g1,      b1,      1},
    {pA,    W2,                 pB,  g2,      b2,      0},
    {pB,    Wk,                 pk0, gk,      bk,      1},
    {pk0,   Wk +   KN*CH*CH,    pk1, gk+CH,   bk+CH,   1},
    {pk1,   Wk + 2*KN*CH*CH,    pk2, gk+2*CH, bk+2*CH, 1},
  };
  for (int s=0;s<5;s++){
    conv_kernel<<<NPTS/128, 256>>>(steps[s].src, nbr, steps[s].W, steps[s].dst);
    clear_stats_kernel<<<1,64>>>();
    stats_kernel<<<128,256>>>(steps[s].dst);
    bn_kernel<<<(NPTS*CH/4)/256, 256>>>(steps[s].dst, steps[s].g, steps[s].b, steps[s].relu);
  }
  clear_seg_kernel<<<1, NB*CAQ>>>();
  seg_kernel<<<200, CAQ>>>(bidx);
  fc_kernel<<<1,256>>>(bidx, fc1w, fc1b, fc2w, fc2b, ksw);
  final_kernel<<<(NPTS*CH)/256, 256>>>(feats, bidx, out);
}

// round 3
// speedup vs baseline: 1.7924x; 1.7924x over previous
#include <cuda_runtime.h>
#include <cuda_bf16.h>
#include <math.h>
#include <float.h>
#include <stdint.h>

#define NPTS 80000
#define CH   64
#define KN   27
#define NB   2
#define NXX  3
#define CAQ  192
#define HID  12

// ---------------- scratch (device globals; no allocation allowed) ----------
__device__ float g_conv[NPTS*CH];
__device__ float g_kx0[NPTS*CH];
__device__ float g_kx1[NPTS*CH];
__device__ float g_kx2[NPTS*CH];
__device__ __nv_bfloat162 g_hiA[NPTS*CH/2];
__device__ __nv_bfloat162 g_loA[NPTS*CH/2];
__device__ __nv_bfloat162 g_hiB[NPTS*CH/2];
__device__ __nv_bfloat162 g_loB[NPTS*CH/2];
__device__ uint32_t g_wswz[5*KN*4096];      // pre-swizzled B tiles: 64n x 128k bf16 (16KB/tap)
__device__ float g_sum[CH], g_sumsq[CH];
__device__ float g_segsum[NB*CAQ], g_segmax[NB*CAQ], g_att[NB*CAQ], g_wsig[NXX];

// ---------------- helpers ----------------------------------------------------
__device__ __forceinline__ uint32_t smem_u32(const void* p){
  uint32_t a;
  asm("{ .reg .u64 t; cvta.to.shared.u64 t, %1; cvt.u32.u64 %0, t; }" : "=r"(a) : "l"(p));
  return a;
}
__device__ __forceinline__ void ldsm_x4(uint32_t addr, uint32_t* r){
  asm volatile("ldmatrix.sync.aligned.m8n8.x4.shared.b16 {%0,%1,%2,%3}, [%4];"
    : "=r"(r[0]),"=r"(r[1]),"=r"(r[2]),"=r"(r[3]) : "r"(addr));
}
__device__ __forceinline__ void hmma(float* c, const uint32_t* a, uint32_t b0, uint32_t b1){
  asm volatile(
    "mma.sync.aligned.m16n8k16.row.col.f32.bf16.bf16.f32 "
    "{%0,%1,%2,%3}, {%4,%5,%6,%7}, {%8,%9}, {%0,%1,%2,%3};"
    : "+f"(c[0]), "+f"(c[1]), "+f"(c[2]), "+f"(c[3])
    : "r"(a[0]), "r"(a[1]), "r"(a[2]), "r"(a[3]), "r"(b0), "r"(b1));
}
__device__ __forceinline__ void cp16(uint32_t sdst, const void* gsrc){
  asm volatile("cp.async.cg.shared.global [%0], [%1], 16;" :: "r"(sdst), "l"(gsrc));
}
__device__ __forceinline__ void cp16z(uint32_t sdst, const void* gsrc, int srcsz){
  asm volatile("cp.async.cg.shared.global [%0], [%1], 16, %2;" :: "r"(sdst), "l"(gsrc), "r"(srcsz));
}
#define CP_COMMIT() asm volatile("cp.async.commit_group;" ::: "memory")
#define CP_WAIT1()  asm volatile("cp.async.wait_group 1;" ::: "memory")

__device__ __forceinline__ void atomicMaxFloat(float* addr, float val){
  int* ai = (int*)addr;
  int old = *ai;
  while (true){
    float fo = __int_as_float(old);
    if (fo >= val) break;
    int assumed = old;
    old = atomicCAS(ai, assumed, __float_as_int(val));
    if (old == assumed) break;
  }
}

// ---------------- weight prep: split fp32 W -> [B_hi|B_lo] swizzled tiles ---
// per tap tile: [n (64 rows)][kk (128 bf16)], row stride 256B.
// kk<64: hi(W[k][kk][n]) ; kk>=64: lo(W[k][kk-64][n]).
// smem byte = n*256 + ((kk>>3) ^ (n&7))*16 + (kk&7)*2
__global__ void wprep_kernel(const float* __restrict__ W1,
                             const float* __restrict__ W2,
                             const float* __restrict__ Wk){
  int gid = blockIdx.x*256 + threadIdx.x;
  if (gid >= 5*KN*4096) return;
  int o  = gid & 4095;
  int tk = gid >> 12;
  int l = tk/KN, k = tk - l*KN;
  const float* Ws = (l==0)? W1 : (l==1)? W2 : (Wk + (size_t)(l-2)*KN*CH*CH);
  int n  = o >> 6;
  int kp = o & 63;
  int kk = kp*2;
  int ci = kk & 63;
  float w0 = Ws[k*CH*CH + ci*CH + n];
  float w1 = Ws[k*CH*CH + (ci+1)*CH + n];
  __nv_bfloat16 b0, b1;
  if (kk < 64){
    b0 = __float2bfloat16(w0); b1 = __float2bfloat16(w1);
  } else {
    __nv_bfloat16 h0 = __float2bfloat16(w0), h1 = __float2bfloat16(w1);
    b0 = __float2bfloat16(w0 - __bfloat162float(h0));
    b1 = __float2bfloat16(w1 - __bfloat162float(h1));
  }
  uint32_t val = (uint32_t)__bfloat16_as_ushort(b0) | ((uint32_t)__bfloat16_as_ushort(b1) << 16);
  uint32_t byte = (uint32_t)n*256 + (uint32_t)(((kk>>3) ^ (n&7))*16) + (uint32_t)((kk&7)*2);
  g_wswz[tk*4096 + (byte>>2)] = val;
}

// ---------------- fp32 -> (hi,lo) bf16 split of layer-0 input ---------------
__global__ void cvt_kernel(const float4* __restrict__ x,
                           __nv_bfloat162* __restrict__ ho,
                           __nv_bfloat162* __restrict__ lo){
  int i4 = blockIdx.x*256 + threadIdx.x;
  float4 v = x[i4];
  __nv_bfloat16 h0=__float2bfloat16(v.x), h1=__float2bfloat16(v.y),
                h2=__float2bfloat16(v.z), h3=__float2bfloat16(v.w);
  ho[2*i4]   = __halves2bfloat162(h0,h1);
  ho[2*i4+1] = __halves2bfloat162(h2,h3);
  lo[2*i4]   = __halves2bfloat162(__float2bfloat16(v.x-__bfloat162float(h0)),
                                  __float2bfloat16(v.y-__bfloat162float(h1)));
  lo[2*i4+1] = __halves2bfloat162(__float2bfloat16(v.z-__bfloat162float(h2)),
                                  __float2bfloat16(v.w-__bfloat162float(h3)));
}

// ---------------- HMMA gathered conv: dst = sum_k gather_k(x) @ W[k] --------
// block: 128 rows x 64 cols. A smem: 128 rows x 128 k bf16 ([hi|lo], 32KB) x2 buf.
// B smem: 64 n x 128 k bf16 ([hi|lo], 16KB) x2 buf. Total 96KB dynamic.
// 12 k-steps of K=16 per tap implement the 3 compensation passes.
#define A_OFF 0
#define B_OFF 65536
#define SM_DYN (98304 + 1024)

__device__ __forceinline__ void issue_tap(
    int k, int buf, int row0, int t, uint32_t sb,
    const __nv_bfloat16* __restrict__ hi, const __nv_bfloat16* __restrict__ lo,
    const int* __restrict__ nbr, const uint32_t* __restrict__ bswz)
{
  // B: linear 16KB copy of pre-swizzled tile
  {
    uint32_t bdst = sb + B_OFF + buf*16384 + t*16;
    const char* bsrc = (const char*)(bswz + (size_t)k*4096) + t*16;
#pragma unroll
    for (int i=0;i<4;i++) cp16(bdst + i*4096, bsrc + i*4096);
  }
  // A: gathered rows; zero-fill when neighbor invalid
  {
    int r = t>>1, half = t&1;
    int idx = __ldg(&nbr[(size_t)(row0+r)*KN + k]);
    int sz = idx>=0 ? 16 : 0;
    int sidx = idx>=0 ? idx : 0;
    const char* asrc = (const char*)((half? lo: hi) + (size_t)sidx*CH);
    uint32_t abase = sb + A_OFF + buf*32768 + (uint32_t)r*256;
    int xr = r & 7;
#pragma unroll
    for (int j=0;j<8;j++){
      int c = half*8 + j;
      int sw = c ^ xr;
      cp16z(abase + sw*16, asrc + j*16, sz);
    }
  }
}

__global__ void __launch_bounds__(256,1) conv_mma(
    const __nv_bfloat16* __restrict__ hi, const __nv_bfloat16* __restrict__ lo,
    const int* __restrict__ nbr, const uint32_t* __restrict__ bswz,
    float* __restrict__ dst)
{
  extern __shared__ char smraw[];
  char* sm = (char*)(((uintptr_t)smraw + 1023) & ~(uintptr_t)1023);
  const uint32_t sb = smem_u32(sm);
  __shared__ float sred[128];

  const int t   = threadIdx.x;
  const int L   = t & 31;
  const int wid = t >> 5;
  const int wm  = wid >> 1;       // 0..3  (M strips of 32 rows)
  const int wn  = wid & 1;        // 0..1  (N halves of 32 cols)
  const int row0 = blockIdx.x * 128;

  if (t < 128) sred[t] = 0.f;

  float acc[2][4][4];
#pragma unroll
  for (int s=0;s<2;s++)
#pragma unroll
    for (int nb=0;nb<4;nb++)
#pragma unroll
      for (int i=0;i<4;i++) acc[s][nb][i]=0.f;

  // lane-constant pieces of ldmatrix addresses
  const int arow_l  = ((L>>3)&1)*8 + (L&7);      // within 16-row strip
  const int a_clane = (L>>4);                    // chunk +0/+1
  const int brow    = wn*32 + (L>>4)*8 + (L&7);  // first 16 n-rows of this warp half
  const int b_clane = ((L>>3)&1);

  // prologue: taps 0,1
  issue_tap(0, 0, row0, t, sb, hi, lo, nbr, bswz); CP_COMMIT();
  issue_tap(1, 1, row0, t, sb, hi, lo, nbr, bswz); CP_COMMIT();

  for (int k = 0; k < KN; k++){
    CP_WAIT1();
    __syncthreads();

    const uint32_t Ab = sb + A_OFF + (k&1)*32768;
    const uint32_t Bb = sb + B_OFF + (k&1)*16384;

#pragma unroll
    for (int ks=0; ks<12; ks++){
      const int p  = ks>>2;
      const int kk = (ks&3)<<4;
      const int ca = (kk + (p==1?64:0)) >> 3;   // A chunk base
      const int cb = (kk + (p==2?64:0)) >> 3;   // B chunk base

      uint32_t Af0[4], Af1[4], Bf0[4], Bf1[4];
      {
        int row = wm*32 + arow_l;               // strip 0
        uint32_t a0 = Ab + (uint32_t)row*256 + (uint32_t)(((ca + a_clane) ^ (row&7))*16);
        ldsm_x4(a0, Af0);
        ldsm_x4(a0 + 16*256, Af1);              // strip 1 (+16 rows, swizzle invariant)
      }
      {
        uint32_t b0 = Bb + (uint32_t)brow*256 + (uint32_t)(((cb + b_clane) ^ (brow&7))*16);
        ldsm_x4(b0, Bf0);                       // nb0, nb1
        ldsm_x4(b0 + 16*256, Bf1);              // nb2, nb3
      }
      hmma(acc[0][0], Af0, Bf0[0], Bf0[1]);
      hmma(acc[0][1], Af0, Bf0[2], Bf0[3]);
      hmma(acc[0][2], Af0, Bf1[0], Bf1[1]);
      hmma(acc[0][3], Af0, Bf1[2], Bf1[3]);
      hmma(acc[1][0], Af1, Bf0[0], Bf0[1]);
      hmma(acc[1][1], Af1, Bf0[2], Bf0[3]);
      hmma(acc[1][2], Af1, Bf1[0], Bf1[1]);
      hmma(acc[1][3], Af1, Bf1[2], Bf1[3]);
    }
    __syncthreads();
    if (k+2 < KN) issue_tap(k+2, k&1, row0, t, sb, hi, lo, nbr, bswz);
    CP_COMMIT();
  }

  // ---- epilogue: stores + fused per-channel stats
#pragma unroll
  for (int s=0;s<2;s++){
    int r = row0 + wm*32 + s*16 + (L>>2);
#pragma unroll
    for (int nb=0;nb<4;nb++){
      int col = wn*32 + nb*8 + (L&3)*2;
      float* c = acc[s][nb];
      *(float2*)&dst[(size_t)r*CH + col]     = make_float2(c[0], c[1]);
      *(float2*)&dst[(size_t)(r+8)*CH + col] = make_float2(c[2], c[3]);
    }
  }
#pragma unroll
  for (int nb=0;nb<4;nb++){
    float sc0=0.f, sc1=0.f, qc0=0.f, qc1=0.f;
#pragma unroll
    for (int s=0;s<2;s++){
      float* c = acc[s][nb];
      sc0 += c[0]+c[2]; qc0 += c[0]*c[0]+c[2]*c[2];
      sc1 += c[1]+c[3]; qc1 += c[1]*c[1]+c[3]*c[3];
    }
#pragma unroll
    for (int m=4;m<32;m<<=1){
      sc0 += __shfl_xor_sync(0xFFFFFFFFu, sc0, m);
      sc1 += __shfl_xor_sync(0xFFFFFFFFu, sc1, m);
      qc0 += __shfl_xor_sync(0xFFFFFFFFu, qc0, m);
      qc1 += __shfl_xor_sync(0xFFFFFFFFu, qc1, m);
    }
    if (L < 4){
      int col = wn*32 + nb*8 + L*2;
      atomicAdd(&sred[col],    sc0); atomicAdd(&sred[col+1],    sc1);
      atomicAdd(&sred[64+col], qc0); atomicAdd(&sred[64+col+1], qc1);
    }
  }
  __syncthreads();
  if (t < 64){
    atomicAdd(&g_sum[t],   sred[t]);
    atomicAdd(&g_sumsq[t], sred[64+t]);
  }
}

// ---------------- stats clear ----------------------------------------------
__global__ void clear_stats_kernel(){
  int t = threadIdx.x; if (t < CH){ g_sum[t]=0.f; g_sumsq[t]=0.f; }
}

// ---------------- BN apply + emit fp32 and/or bf16 hi/lo --------------------
__global__ void bn2_kernel(const float* __restrict__ x, const float* __restrict__ gg,
                           const float* __restrict__ bb, int relu,
                           float* __restrict__ fout,
                           __nv_bfloat162* __restrict__ ho,
                           __nv_bfloat162* __restrict__ lo){
  __shared__ float sc[64], bi[64];
  int t = threadIdx.x;
  if (t < 64){
    float m = g_sum[t]*(1.f/NPTS);
    float v = g_sumsq[t]*(1.f/NPTS) - m*m;
    float s = rsqrtf(v + 1e-5f) * gg[t];
    sc[t] = s; bi[t] = bb[t] - m*s;
  }
  __syncthreads();
  int i4 = blockIdx.x*256 + t;
  float4 v = ((const float4*)x)[i4];
  int c = (i4 & 15)*4;
  v.x = v.x*sc[c]+bi[c];     v.y = v.y*sc[c+1]+bi[c+1];
  v.z = v.z*sc[c+2]+bi[c+2]; v.w = v.w*sc[c+3]+bi[c+3];
  if (relu){ v.x=fmaxf(v.x,0.f); v.y=fmaxf(v.y,0.f); v.z=fmaxf(v.z,0.f); v.w=fmaxf(v.w,0.f); }
  if (fout) ((float4*)fout)[i4] = v;
  if (ho){
    __nv_bfloat16 h0=__float2bfloat16(v.x), h1=__float2bfloat16(v.y),
                  h2=__float2bfloat16(v.z), h3=__float2bfloat16(v.w);
    ho[2*i4]   = __halves2bfloat162(h0,h1);
    ho[2*i4+1] = __halves2bfloat162(h2,h3);
    lo[2*i4]   = __halves2bfloat162(__float2bfloat16(v.x-__bfloat162float(h0)),
                                    __float2bfloat16(v.y-__bfloat162float(h1)));
    lo[2*i4+1] = __halves2bfloat162(__float2bfloat16(v.z-__bfloat162float(h2)),
                                    __float2bfloat16(v.w-__bfloat162float(h3)));
  }
}

// ---------------- segment sum/max over batches (B=2), 192 channels ---------
__global__ void clear_seg_kernel(){
  int t = threadIdx.x; if (t < NB*CAQ){ g_segsum[t]=0.f; g_segmax[t]=-FLT_MAX; }
}
__global__ void seg_kernel(const int* __restrict__ bidx){
  int j = threadIdx.x;
  const float* kxp = (j<64)? g_kx0 : ((j<128)? g_kx1 : g_kx2);
  int c = j & 63;
  int n0 = blockIdx.x*400, n1 = n0+400;
  float s0=0.f, s1=0.f, m0=-FLT_MAX, m1=-FLT_MAX;
  for (int n=n0;n<n1;n++){
    float v = kxp[n*CH + c];
    if (bidx[n]==0){ s0+=v; m0=fmaxf(m0,v); } else { s1+=v; m1=fmaxf(m1,v); }
  }
  atomicAdd(&g_segsum[j], s0);
  atomicAdd(&g_segsum[CAQ+j], s1);
  atomicMaxFloat(&g_segmax[j], m0);
  atomicMaxFloat(&g_segmax[CAQ+j], m1);
}

// ---------------- tiny FC + sigmoid attention ------------------------------
__global__ void fc_kernel(const int* __restrict__ bidx,
    const float* __restrict__ w1, const float* __restrict__ b1,
    const float* __restrict__ w2, const float* __restrict__ b2,
    const float* __restrict__ ksw)
{
  __shared__ float ha[NB][HID], hm[NB][HID];
  __shared__ int red[256];
  __shared__ int scnt[NB];
  int t = threadIdx.x;
  int c0 = 0;
  for (int n=t; n<NPTS; n+=256) c0 += (bidx[n]==0);
  red[t]=c0; __syncthreads();
  for (int s=128;s>0;s>>=1){ if (t<s) red[t]+=red[t+s]; __syncthreads(); }
  if (t==0){ scnt[0]=red[0]; scnt[1]=NPTS-red[0]; }
  __syncthreads();
  if (t<48){
    int which = t/24;
    int b  = (t/12)%2;
    int tt = t%12;
    float s = b1[tt];
    float inv = 1.f/(float)scnt[b];
    for (int j=0;j<CAQ;j++){
      float z = which ? g_segmax[b*CAQ+j] : g_segsum[b*CAQ+j]*inv;
      s += z * w1[j*HID+tt];
    }
    s = fmaxf(s,0.f);
    if (which) hm[b][tt]=s; else ha[b][tt]=s;
  }
  __syncthreads();
  for (int o=t; o<NB*CAQ; o+=256){
    int b=o/CAQ, j=o%CAQ;
    float sa=b2[j], sm=b2[j];
    for (int tt=0;tt<HID;tt++){ sa += ha[b][tt]*w2[tt*CAQ+j]; sm += hm[b][tt]*w2[tt*CAQ+j]; }
    float s = sa+sm;
    g_att[o] = 1.f/(1.f+expf(-s));
  }
  if (t<NXX) g_wsig[t] = 1.f/(1.f+expf(-ksw[t]));
}

// ---------------- fusion epilogue ------------------------------------------
__device__ __forceinline__ float kx_read(int sel, int off){
  return sel==0 ? g_kx0[off] : (sel==1 ? g_kx1[off] : g_kx2[off]);
}
__global__ void final_kernel(const float* __restrict__ feats,
                             const int* __restrict__ bidx,
                             float* __restrict__ out){
  int i = blockIdx.x*256 + threadIdx.x;
  int n = i >> 6, c = i & 63;
  int b = bidx[n];
  float acc = feats[i];
#pragma unroll
  for (int ii=0; ii<NXX; ii++){
    int j = 3*c + ii;
    int sel = j >> 6, col = j & 63;
    float xj  = kx_read(sel, n*CH + col);
    float kxi = kx_read(ii, i);
    acc += g_wsig[ii] * (kxi + xj * g_att[b*CAQ + j]);
  }
  out[i] = fmaxf(acc, 0.f);
}

// ---------------- launch ----------------------------------------------------
extern "C" void kernel_launch(void* const* d_in, const int* in_sizes, int n_in,
                              void* d_out, int out_size){
  (void)in_sizes; (void)n_in; (void)out_size;
  const float* feats=(const float*)d_in[0];
  const int*   bidx =(const int*)d_in[1];
  const int*   nbr  =(const int*)d_in[2];
  const float* W1 =(const float*)d_in[3];
  const float* g1 =(const float*)d_in[4];
  const float* b1 =(const float*)d_in[5];
  const float* W2 =(const float*)d_in[6];
  const float* g2 =(const float*)d_in[7];
  const float* b2 =(const float*)d_in[8];
  const float* Wk =(const float*)d_in[9];
  const float* gk =(const float*)d_in[10];
  const float* bk =(const float*)d_in[11];
  const float* fc1w=(const float*)d_in[12];
  const float* fc1b=(const float*)d_in[13];
  const float* fc2w=(const float*)d_in[14];
  const float* fc2b=(const float*)d_in[15];
  const float* ksw =(const float*)d_in[16];
  float* out=(float*)d_out;

  float *pConv,*pk0,*pk1,*pk2;
  __nv_bfloat162 *pHiA,*pLoA,*pHiB,*pLoB;
  uint32_t* pW;
  cudaGetSymbolAddress((void**)&pConv, g_conv);
  cudaGetSymbolAddress((void**)&pk0, g_kx0);
  cudaGetSymbolAddress((void**)&pk1, g_kx1);
  cudaGetSymbolAddress((void**)&pk2, g_kx2);
  cudaGetSymbolAddress((void**)&pHiA, g_hiA);
  cudaGetSymbolAddress((void**)&pLoA, g_loA);
  cudaGetSymbolAddress((void**)&pHiB, g_hiB);
  cudaGetSymbolAddress((void**)&pLoB, g_loB);
  cudaGetSymbolAddress((void**)&pW,  g_wswz);

  cudaFuncSetAttribute(conv_mma, cudaFuncAttributeMaxDynamicSharedMemorySize, SM_DYN);

  wprep_kernel<<<(5*KN*4096 + 255)/256, 256>>>(W1, W2, Wk);
  cvt_kernel<<<NPTS*CH/4/256, 256>>>((const float4*)feats, pHiA, pLoA);

  struct Step {
    const __nv_bfloat16 *hi, *lo; const uint32_t* bw;
    const float *g, *b; int relu;
    float* fout; __nv_bfloat162 *ho, *loo;
  };
  Step steps[5] = {
    {(const __nv_bfloat16*)pHiA,(const __nv_bfloat16*)pLoA, pW + 0*KN*4096, g1,      b1,      1, nullptr, pHiB, pLoB},
    {(const __nv_bfloat16*)pHiB,(const __nv_bfloat16*)pLoB, pW + 1*KN*4096, g2,      b2,      0, nullptr, pHiA, pLoA},
    {(const __nv_bfloat16*)pHiA,(const __nv_bfloat16*)pLoA, pW + 2*KN*4096, gk,      bk,      1, pk0,     pHiB, pLoB},
    {(const __nv_bfloat16*)pHiB,(const __nv_bfloat16*)pLoB, pW + 3*KN*4096, gk+CH,   bk+CH,   1, pk1,     pHiA, pLoA},
    {(const __nv_bfloat16*)pHiA,(const __nv_bfloat16*)pLoA, pW + 4*KN*4096, gk+2*CH, bk+2*CH, 1, pk2,     nullptr, nullptr},
  };
  for (int s=0;s<5;s++){
    clear_stats_kernel<<<1,64>>>();
    conv_mma<<<NPTS/128, 256, SM_DYN>>>(steps[s].hi, steps[s].lo, nbr, steps[s].bw, pConv);
    bn2_kernel<<<NPTS*CH/4/256, 256>>>(pConv, steps[s].g, steps[s].b, steps[s].relu,
                                       steps[s].fout, steps[s].ho, steps[s].loo);
  }
  clear_seg_kernel<<<1, NB*CAQ>>>();
  seg_kernel<<<200, CAQ>>>(bidx);
  fc_kernel<<<1,256>>>(bidx, fc1w, fc1b, fc2w, fc2b, ksw);
  final_kernel<<<(NPTS*CH)/256, 256>>>(feats, bidx, out);
}

// round 4
// speedup vs baseline: 2.0795x; 1.1602x over previous
#include <cuda_runtime.h>
#include <cuda_bf16.h>
#include <math.h>
#include <float.h>
#include <stdint.h>

#define NPTS 80000
#define CH   64
#define KN   27
#define NB   2
#define NXX  3
#define CAQ  192
#define HID  12

// ---------------- scratch (device globals; no allocation allowed) ----------
__device__ float g_conv[NPTS*CH];
__device__ float g_kx0[NPTS*CH];
__device__ float g_kx1[NPTS*CH];
__device__ float g_kx2[NPTS*CH];
__device__ __nv_bfloat162 g_hiA[NPTS*CH/2];
__device__ __nv_bfloat162 g_loA[NPTS*CH/2];
__device__ __nv_bfloat162 g_hiB[NPTS*CH/2];
__device__ __nv_bfloat162 g_loB[NPTS*CH/2];
__device__ uint32_t g_wswz[5*KN*4096];      // pre-swizzled B tiles: 64n x 128k bf16 (16KB/tap)
__device__ float g_sum[CH], g_sumsq[CH];
__device__ float g_segsum[NB*CAQ], g_segmax[NB*CAQ], g_att[NB*CAQ], g_wsig[NXX];

// ---------------- helpers ----------------------------------------------------
__device__ __forceinline__ uint32_t smem_u32(const void* p){
  uint32_t a;
  asm("{ .reg .u64 t; cvta.to.shared.u64 t, %1; cvt.u32.u64 %0, t; }" : "=r"(a) : "l"(p));
  return a;
}
__device__ __forceinline__ void ldsm_x4(uint32_t addr, uint32_t* r){
  asm volatile("ldmatrix.sync.aligned.m8n8.x4.shared.b16 {%0,%1,%2,%3}, [%4];"
    : "=r"(r[0]),"=r"(r[1]),"=r"(r[2]),"=r"(r[3]) : "r"(addr));
}
__device__ __forceinline__ void hmma(float* c, const uint32_t* a, uint32_t b0, uint32_t b1){
  asm volatile(
    "mma.sync.aligned.m16n8k16.row.col.f32.bf16.bf16.f32 "
    "{%0,%1,%2,%3}, {%4,%5,%6,%7}, {%8,%9}, {%0,%1,%2,%3};"
    : "+f"(c[0]), "+f"(c[1]), "+f"(c[2]), "+f"(c[3])
    : "r"(a[0]), "r"(a[1]), "r"(a[2]), "r"(a[3]), "r"(b0), "r"(b1));
}
__device__ __forceinline__ void cp16(uint32_t sdst, const void* gsrc){
  asm volatile("cp.async.cg.shared.global [%0], [%1], 16;" :: "r"(sdst), "l"(gsrc));
}
__device__ __forceinline__ void cp16z(uint32_t sdst, const void* gsrc, int srcsz){
  asm volatile("cp.async.cg.shared.global [%0], [%1], 16, %2;" :: "r"(sdst), "l"(gsrc), "r"(srcsz));
}
#define CP_COMMIT() asm volatile("cp.async.commit_group;" ::: "memory")
#define CP_WAIT1()  asm volatile("cp.async.wait_group 1;" ::: "memory")

__device__ __forceinline__ void atomicMaxFloat(float* addr, float val){
  int* ai = (int*)addr;
  int old = *ai;
  while (true){
    float fo = __int_as_float(old);
    if (fo >= val) break;
    int assumed = old;
    old = atomicCAS(ai, assumed, __float_as_int(val));
    if (old == assumed) break;
  }
}

// ---------------- weight prep: split fp32 W -> [B_hi|B_lo] swizzled tiles ---
__global__ void wprep_kernel(const float* __restrict__ W1,
                             const float* __restrict__ W2,
                             const float* __restrict__ Wk){
  int gid = blockIdx.x*256 + threadIdx.x;
  if (gid >= 5*KN*4096) return;
  int o  = gid & 4095;
  int tk = gid >> 12;
  int l = tk/KN, k = tk - l*KN;
  const float* Ws = (l==0)? W1 : (l==1)? W2 : (Wk + (size_t)(l-2)*KN*CH*CH);
  int n  = o >> 6;
  int kp = o & 63;
  int kk = kp*2;
  int ci = kk & 63;
  float w0 = Ws[k*CH*CH + ci*CH + n];
  float w1 = Ws[k*CH*CH + (ci+1)*CH + n];
  __nv_bfloat16 b0, b1;
  if (kk < 64){
    b0 = __float2bfloat16(w0); b1 = __float2bfloat16(w1);
  } else {
    __nv_bfloat16 h0 = __float2bfloat16(w0), h1 = __float2bfloat16(w1);
    b0 = __float2bfloat16(w0 - __bfloat162float(h0));
    b1 = __float2bfloat16(w1 - __bfloat162float(h1));
  }
  uint32_t val = (uint32_t)__bfloat16_as_ushort(b0) | ((uint32_t)__bfloat16_as_ushort(b1) << 16);
  uint32_t byte = (uint32_t)n*256 + (uint32_t)(((kk>>3) ^ (n&7))*16) + (uint32_t)((kk&7)*2);
  g_wswz[tk*4096 + (byte>>2)] = val;
}

// ---------------- fp32 -> (hi,lo) bf16 split of layer-0 input ---------------
__global__ void cvt_kernel(const float4* __restrict__ x,
                           __nv_bfloat162* __restrict__ ho,
                           __nv_bfloat162* __restrict__ lo){
  int i4 = blockIdx.x*256 + threadIdx.x;
  float4 v = x[i4];
  __nv_bfloat16 h0=__float2bfloat16(v.x), h1=__float2bfloat16(v.y),
                h2=__float2bfloat16(v.z), h3=__float2bfloat16(v.w);
  ho[2*i4]   = __halves2bfloat162(h0,h1);
  ho[2*i4+1] = __halves2bfloat162(h2,h3);
  lo[2*i4]   = __halves2bfloat162(__float2bfloat16(v.x-__bfloat162float(h0)),
                                  __float2bfloat16(v.y-__bfloat162float(h1)));
  lo[2*i4+1] = __halves2bfloat162(__float2bfloat16(v.z-__bfloat162float(h2)),
                                  __float2bfloat16(v.w-__bfloat162float(h3)));
}

// ---------------- HMMA gathered conv -----------------------------------------
#define A_OFF 0
#define B_OFF 65536
#define SM_DYN (98304 + 1024)

__device__ __forceinline__ void issue_tap(
    int k, int buf, int row0, int t, uint32_t sb,
    const __nv_bfloat16* __restrict__ hi, const __nv_bfloat16* __restrict__ lo,
    const int* __restrict__ nbr, const uint32_t* __restrict__ bswz)
{
  // B: linear 16KB copy of pre-swizzled tile
  {
    uint32_t bdst = sb + B_OFF + buf*16384 + t*16;
    const char* bsrc = (const char*)(bswz + (size_t)k*4096) + t*16;
#pragma unroll
    for (int i=0;i<4;i++) cp16(bdst + i*4096, bsrc + i*4096);
  }
  // A: gathered rows; zero-fill when neighbor invalid
  {
    int r = t>>1, half = t&1;
    int idx = __ldg(&nbr[(size_t)(row0+r)*KN + k]);
    int sz = idx>=0 ? 16 : 0;
    int sidx = idx>=0 ? idx : 0;
    const char* asrc = (const char*)((half? lo: hi) + (size_t)sidx*CH);
    uint32_t abase = sb + A_OFF + buf*32768 + (uint32_t)r*256;
    int xr = r & 7;
#pragma unroll
    for (int j=0;j<8;j++){
      int c = half*8 + j;
      int sw = c ^ xr;
      cp16z(abase + sw*16, asrc + j*16, sz);
    }
  }
}

__global__ void __launch_bounds__(256,2) conv_mma(
    const __nv_bfloat16* __restrict__ hi, const __nv_bfloat16* __restrict__ lo,
    const int* __restrict__ nbr, const uint32_t* __restrict__ bswz,
    float* __restrict__ dst)
{
  extern __shared__ char smraw[];
  char* sm = (char*)(((uintptr_t)smraw + 1023) & ~(uintptr_t)1023);
  const uint32_t sb = smem_u32(sm);
  __shared__ float sred[128];

  const int t   = threadIdx.x;
  const int L   = t & 31;
  const int wid = t >> 5;
  const int wm  = wid >> 1;       // 0..3  (M strips of 32 rows)
  const int wn  = wid & 1;        // 0..1  (N halves of 32 cols)
  const int row0 = blockIdx.x * 128;

  if (t < 128) sred[t] = 0.f;

  float acc[2][4][4];
#pragma unroll
  for (int s=0;s<2;s++)
#pragma unroll
    for (int nb=0;nb<4;nb++)
#pragma unroll
      for (int i=0;i<4;i++) acc[s][nb][i]=0.f;

  // lane-constant ldmatrix address pieces
  const int arow_l  = ((L>>3)&1)*8 + (L&7);
  const int a_clane = (L>>4);
  const int brow    = wn*32 + (L>>4)*8 + (L&7);
  const int b_clane = ((L>>3)&1);
  const int arow    = wm*32 + arow_l;
  const int axor    = arow & 7;
  const int bxor    = brow & 7;

  issue_tap(0, 0, row0, t, sb, hi, lo, nbr, bswz); CP_COMMIT();
  issue_tap(1, 1, row0, t, sb, hi, lo, nbr, bswz); CP_COMMIT();

  for (int k = 0; k < KN; k++){
    CP_WAIT1();
    __syncthreads();

    const uint32_t Arow = sb + A_OFF + (k&1)*32768 + (uint32_t)arow*256;
    const uint32_t Brow = sb + B_OFF + (k&1)*16384 + (uint32_t)brow*256;

#pragma unroll
    for (int q=0; q<4; q++){
      const int c_hi = q*2;        // hi chunk pair base
      const int c_lo = c_hi + 8;   // lo chunk pair base

      uint32_t Ah0[4], Ah1[4], Bh0[4], Bh1[4], T0[4], T1[4];
      uint32_t ah = Arow + (uint32_t)(((c_hi + a_clane) ^ axor)*16);
      ldsm_x4(ah, Ah0);
      ldsm_x4(ah + 16*256, Ah1);
      uint32_t bh = Brow + (uint32_t)(((c_hi + b_clane) ^ bxor)*16);
      ldsm_x4(bh, Bh0);
      ldsm_x4(bh + 16*256, Bh1);

      // pass 0: A_hi x B_hi
      hmma(acc[0][0], Ah0, Bh0[0], Bh0[1]);
      hmma(acc[0][1], Ah0, Bh0[2], Bh0[3]);
      hmma(acc[0][2], Ah0, Bh1[0], Bh1[1]);
      hmma(acc[0][3], Ah0, Bh1[2], Bh1[3]);
      hmma(acc[1][0], Ah1, Bh0[0], Bh0[1]);
      hmma(acc[1][1], Ah1, Bh0[2], Bh0[3]);
      hmma(acc[1][2], Ah1, Bh1[0], Bh1[1]);
      hmma(acc[1][3], Ah1, Bh1[2], Bh1[3]);

      // pass 1: A_lo x B_hi
      uint32_t al = Arow + (uint32_t)(((c_lo + a_clane) ^ axor)*16);
      ldsm_x4(al, T0);
      ldsm_x4(al + 16*256, T1);
      hmma(acc[0][0], T0, Bh0[0], Bh0[1]);
      hmma(acc[0][1], T0, Bh0[2], Bh0[3]);
      hmma(acc[0][2], T0, Bh1[0], Bh1[1]);
      hmma(acc[0][3], T0, Bh1[2], Bh1[3]);
      hmma(acc[1][0], T1, Bh0[0], Bh0[1]);
      hmma(acc[1][1], T1, Bh0[2], Bh0[3]);
      hmma(acc[1][2], T1, Bh1[0], Bh1[1]);
      hmma(acc[1][3], T1, Bh1[2], Bh1[3]);

      // pass 2: A_hi x B_lo
      uint32_t bl = Brow + (uint32_t)(((c_lo + b_clane) ^ bxor)*16);
      ldsm_x4(bl, T0);
      ldsm_x4(bl + 16*256, T1);
      hmma(acc[0][0], Ah0, T0[0], T0[1]);
      hmma(acc[0][1], Ah0, T0[2], T0[3]);
      hmma(acc[0][2], Ah0, T1[0], T1[1]);
      hmma(acc[0][3], Ah0, T1[2], T1[3]);
      hmma(acc[1][0], Ah1, T0[0], T0[1]);
      hmma(acc[1][1], Ah1, T0[2], T0[3]);
      hmma(acc[1][2], Ah1, T1[0], T1[1]);
      hmma(acc[1][3], Ah1, T1[2], T1[3]);
    }
    __syncthreads();
    if (k+2 < KN) issue_tap(k+2, k&1, row0, t, sb, hi, lo, nbr, bswz);
    CP_COMMIT();
  }

  // ---- epilogue: stores + fused per-channel stats
#pragma unroll
  for (int s=0;s<2;s++){
    int r = row0 + wm*32 + s*16 + (L>>2);
#pragma unroll
    for (int nb=0;nb<4;nb++){
      int col = wn*32 + nb*8 + (L&3)*2;
      float* c = acc[s][nb];
      *(float2*)&dst[(size_t)r*CH + col]     = make_float2(c[0], c[1]);
      *(float2*)&dst[(size_t)(r+8)*CH + col] = make_float2(c[2], c[3]);
    }
  }
#pragma unroll
  for (int nb=0;nb<4;nb++){
    float sc0=0.f, sc1=0.f, qc0=0.f, qc1=0.f;
#pragma unroll
    for (int s=0;s<2;s++){
      float* c = acc[s][nb];
      sc0 += c[0]+c[2]; qc0 += c[0]*c[0]+c[2]*c[2];
      sc1 += c[1]+c[3]; qc1 += c[1]*c[1]+c[3]*c[3];
    }
#pragma unroll
    for (int m=4;m<32;m<<=1){
      sc0 += __shfl_xor_sync(0xFFFFFFFFu, sc0, m);
      sc1 += __shfl_xor_sync(0xFFFFFFFFu, sc1, m);
      qc0 += __shfl_xor_sync(0xFFFFFFFFu, qc0, m);
      qc1 += __shfl_xor_sync(0xFFFFFFFFu, qc1, m);
    }
    if (L < 4){
      int col = wn*32 + nb*8 + L*2;
      atomicAdd(&sred[col],    sc0); atomicAdd(&sred[col+1],    sc1);
      atomicAdd(&sred[64+col], qc0); atomicAdd(&sred[64+col+1], qc1);
    }
  }
  __syncthreads();
  if (t < 64){
    atomicAdd(&g_sum[t],   sred[t]);
    atomicAdd(&g_sumsq[t], sred[64+t]);
  }
}

// ---------------- stats clear ----------------------------------------------
__global__ void clear_stats_kernel(){
  int t = threadIdx.x; if (t < CH){ g_sum[t]=0.f; g_sumsq[t]=0.f; }
}

// ---------------- BN apply + emit fp32 and/or bf16 hi/lo --------------------
__global__ void bn2_kernel(const float* __restrict__ x, const float* __restrict__ gg,
                           const float* __restrict__ bb, int relu,
                           float* __restrict__ fout,
                           __nv_bfloat162* __restrict__ ho,
                           __nv_bfloat162* __restrict__ lo){
  __shared__ float sc[64], bi[64];
  int t = threadIdx.x;
  if (t < 64){
    float m = g_sum[t]*(1.f/NPTS);
    float v = g_sumsq[t]*(1.f/NPTS) - m*m;
    float s = rsqrtf(v + 1e-5f) * gg[t];
    sc[t] = s; bi[t] = bb[t] - m*s;
  }
  __syncthreads();
  int i4 = blockIdx.x*256 + t;
  float4 v = ((const float4*)x)[i4];
  int c = (i4 & 15)*4;
  v.x = v.x*sc[c]+bi[c];     v.y = v.y*sc[c+1]+bi[c+1];
  v.z = v.z*sc[c+2]+bi[c+2]; v.w = v.w*sc[c+3]+bi[c+3];
  if (relu){ v.x=fmaxf(v.x,0.f); v.y=fmaxf(v.y,0.f); v.z=fmaxf(v.z,0.f); v.w=fmaxf(v.w,0.f); }
  if (fout) ((float4*)fout)[i4] = v;
  if (ho){
    __nv_bfloat16 h0=__float2bfloat16(v.x), h1=__float2bfloat16(v.y),
                  h2=__float2bfloat16(v.z), h3=__float2bfloat16(v.w);
    ho[2*i4]   = __halves2bfloat162(h0,h1);
    ho[2*i4+1] = __halves2bfloat162(h2,h3);
    lo[2*i4]   = __halves2bfloat162(__float2bfloat16(v.x-__bfloat162float(h0)),
                                    __float2bfloat16(v.y-__bfloat162float(h1)));
    lo[2*i4+1] = __halves2bfloat162(__float2bfloat16(v.z-__bfloat162float(h2)),
                                    __float2bfloat16(v.w-__bfloat162float(h3)));
  }
}

// ---------------- segment sum/max over batches (B=2), 192 channels ---------
__global__ void clear_seg_kernel(){
  int t = threadIdx.x; if (t < NB*CAQ){ g_segsum[t]=0.f; g_segmax[t]=-FLT_MAX; }
}
__global__ void seg_kernel(const int* __restrict__ bidx){
  int j = threadIdx.x;
  const float* kxp = (j<64)? g_kx0 : ((j<128)? g_kx1 : g_kx2);
  int c = j & 63;
  int n0 = blockIdx.x*400, n1 = n0+400;
  float s0=0.f, s1=0.f, m0=-FLT_MAX, m1=-FLT_MAX;
  for (int n=n0;n<n1;n++){
    float v = kxp[n*CH + c];
    if (bidx[n]==0){ s0+=v; m0=fmaxf(m0,v); } else { s1+=v; m1=fmaxf(m1,v); }
  }
  atomicAdd(&g_segsum[j], s0);
  atomicAdd(&g_segsum[CAQ+j], s1);
  atomicMaxFloat(&g_segmax[j], m0);
  atomicMaxFloat(&g_segmax[CAQ+j], m1);
}

// ---------------- tiny FC + sigmoid attention ------------------------------
__global__ void fc_kernel(const int* __restrict__ bidx,
    const float* __restrict__ w1, const float* __restrict__ b1,
    const float* __restrict__ w2, const float* __restrict__ b2,
    const float* __restrict__ ksw)
{
  __shared__ float ha[NB][HID], hm[NB][HID];
  __shared__ int red[256];
  __shared__ int scnt[NB];
  int t = threadIdx.x;
  int c0 = 0;
  for (int n=t; n<NPTS; n+=256) c0 += (bidx[n]==0);
  red[t]=c0; __syncthreads();
  for (int s=128;s>0;s>>=1){ if (t<s) red[t]+=red[t+s]; __syncthreads(); }
  if (t==0){ scnt[0]=red[0]; scnt[1]=NPTS-red[0]; }
  __syncthreads();
  if (t<48){
    int which = t/24;
    int b  = (t/12)%2;
    int tt = t%12;
    float s = b1[tt];
    float inv = 1.f/(float)scnt[b];
    for (int j=0;j<CAQ;j++){
      float z = which ? g_segmax[b*CAQ+j] : g_segsum[b*CAQ+j]*inv;
      s += z * w1[j*HID+tt];
    }
    s = fmaxf(s,0.f);
    if (which) hm[b][tt]=s; else ha[b][tt]=s;
  }
  __syncthreads();
  for (int o=t; o<NB*CAQ; o+=256){
    int b=o/CAQ, j=o%CAQ;
    float sa=b2[j], sm=b2[j];
    for (int tt=0;tt<HID;tt++){ sa += ha[b][tt]*w2[tt*CAQ+j]; sm += hm[b][tt]*w2[tt*CAQ+j]; }
    float s = sa+sm;
    g_att[o] = 1.f/(1.f+expf(-s));
  }
  if (t<NXX) g_wsig[t] = 1.f/(1.f+expf(-ksw[t]));
}

// ---------------- fusion epilogue ------------------------------------------
__device__ __forceinline__ float kx_read(int sel, int off){
  return sel==0 ? g_kx0[off] : (sel==1 ? g_kx1[off] : g_kx2[off]);
}
__global__ void final_kernel(const float* __restrict__ feats,
                             const int* __restrict__ bidx,
                             float* __restrict__ out){
  int i = blockIdx.x*256 + threadIdx.x;
  int n = i >> 6, c = i & 63;
  int b = bidx[n];
  float acc = feats[i];
#pragma unroll
  for (int ii=0; ii<NXX; ii++){
    int j = 3*c + ii;
    int sel = j >> 6, col = j & 63;
    float xj  = kx_read(sel, n*CH + col);
    float kxi = kx_read(ii, i);
    acc += g_wsig[ii] * (kxi + xj * g_att[b*CAQ + j]);
  }
  out[i] = fmaxf(acc, 0.f);
}

// ---------------- launch ----------------------------------------------------
extern "C" void kernel_launch(void* const* d_in, const int* in_sizes, int n_in,
                              void* d_out, int out_size){
  (void)in_sizes; (void)n_in; (void)out_size;
  const float* feats=(const float*)d_in[0];
  const int*   bidx =(const int*)d_in[1];
  const int*   nbr  =(const int*)d_in[2];
  const float* W1 =(const float*)d_in[3];
  const float* g1 =(const float*)d_in[4];
  const float* b1 =(const float*)d_in[5];
  const float* W2 =(const float*)d_in[6];
  const float* g2 =(const float*)d_in[7];
  const float* b2 =(const float*)d_in[8];
  const float* Wk =(const float*)d_in[9];
  const float* gk =(const float*)d_in[10];
  const float* bk =(const float*)d_in[11];
  const float* fc1w=(const float*)d_in[12];
  const float* fc1b=(const float*)d_in[13];
  const float* fc2w=(const float*)d_in[14];
  const float* fc2b=(const float*)d_in[15];
  const float* ksw =(const float*)d_in[16];
  float* out=(float*)d_out;

  float *pConv,*pk0,*pk1,*pk2;
  __nv_bfloat162 *pHiA,*pLoA,*pHiB,*pLoB;
  uint32_t* pW;
  cudaGetSymbolAddress((void**)&pConv, g_conv);
  cudaGetSymbolAddress((void**)&pk0, g_kx0);
  cudaGetSymbolAddress((void**)&pk1, g_kx1);
  cudaGetSymbolAddress((void**)&pk2, g_kx2);
  cudaGetSymbolAddress((void**)&pHiA, g_hiA);
  cudaGetSymbolAddress((void**)&pLoA, g_loA);
  cudaGetSymbolAddress((void**)&pHiB, g_hiB);
  cudaGetSymbolAddress((void**)&pLoB, g_loB);
  cudaGetSymbolAddress((void**)&pW,  g_wswz);

  cudaFuncSetAttribute(conv_mma, cudaFuncAttributeMaxDynamicSharedMemorySize, SM_DYN);

  wprep_kernel<<<(5*KN*4096 + 255)/256, 256>>>(W1, W2, Wk);
  cvt_kernel<<<NPTS*CH/4/256, 256>>>((const float4*)feats, pHiA, pLoA);

  struct Step {
    const __nv_bfloat16 *hi, *lo; const uint32_t* bw;
    const float *g, *b; int relu;
    float* fout; __nv_bfloat162 *ho, *loo;
  };
  Step steps[5] = {
    {(const __nv_bfloat16*)pHiA,(const __nv_bfloat16*)pLoA, pW + 0*KN*4096, g1,      b1,      1, nullptr, pHiB, pLoB},
    {(const __nv_bfloat16*)pHiB,(const __nv_bfloat16*)pLoB, pW + 1*KN*4096, g2,      b2,      0, nullptr, pHiA, pLoA},
    {(const __nv_bfloat16*)pHiA,(const __nv_bfloat16*)pLoA, pW + 2*KN*4096, gk,      bk,      1, pk0,     pHiB, pLoB},
    {(const __nv_bfloat16*)pHiB,(const __nv_bfloat16*)pLoB, pW + 3*KN*4096, gk+CH,   bk+CH,   1, pk1,     pHiA, pLoA},
    {(const __nv_bfloat16*)pHiA,(const __nv_bfloat16*)pLoA, pW + 4*KN*4096, gk+2*CH, bk+2*CH, 1, pk2,     nullptr, nullptr},
  };
  for (int s=0;s<5;s++){
    clear_stats_kernel<<<1,64>>>();
    conv_mma<<<NPTS/128, 256, SM_DYN>>>(steps[s].hi, steps[s].lo, nbr, steps[s].bw, pConv);
    bn2_kernel<<<NPTS*CH/4/256, 256>>>(pConv, steps[s].g, steps[s].b, steps[s].relu,
                                       steps[s].fout, steps[s].ho, steps[s].loo);
  }
  clear_seg_kernel<<<1, NB*CAQ>>>();
  seg_kernel<<<200, CAQ>>>(bidx);
  fc_kernel<<<1,256>>>(bidx, fc1w, fc1b, fc2w, fc2b, ksw);
  final_kernel<<<(NPTS*CH)/256, 256>>>(feats, bidx, out);
}

// round 5
// speedup vs baseline: 2.4408x; 1.1738x over previous
#include <cuda_runtime.h>
#include <cuda_bf16.h>
#include <math.h>
#include <float.h>
#include <stdint.h>

#define NPTS 80000
#define CH   64
#define KN   27
#define NB   2
#define NXX  3
#define CAQ  192
#define HID  12

// ---------------- scratch (device globals; no allocation allowed) ----------
__device__ float g_conv[NPTS*CH];
__device__ float g_kx0[NPTS*CH];
__device__ float g_kx1[NPTS*CH];
__device__ float g_kx2[NPTS*CH];
__device__ __nv_bfloat162 g_hiA[NPTS*CH/2];
__device__ __nv_bfloat162 g_loA[NPTS*CH/2];
__device__ __nv_bfloat162 g_hiB[NPTS*CH/2];
__device__ __nv_bfloat162 g_loB[NPTS*CH/2];
__device__ uint32_t g_wswz[5*KN*4096];      // B tiles packed in mma fragment order (16KB/tap)
__device__ float g_sum[CH], g_sumsq[CH];
__device__ float g_segsum[NB*CAQ], g_segmax[NB*CAQ], g_att[NB*CAQ], g_wsig[NXX];

// ---------------- helpers ----------------------------------------------------
__device__ __forceinline__ uint32_t smem_u32(const void* p){
  uint32_t a;
  asm("{ .reg .u64 t; cvta.to.shared.u64 t, %1; cvt.u32.u64 %0, t; }" : "=r"(a) : "l"(p));
  return a;
}
__device__ __forceinline__ void ldsm_x4(uint32_t addr, uint32_t* r){
  asm volatile("ldmatrix.sync.aligned.m8n8.x4.shared.b16 {%0,%1,%2,%3}, [%4];"
    : "=r"(r[0]),"=r"(r[1]),"=r"(r[2]),"=r"(r[3]) : "r"(addr));
}
__device__ __forceinline__ void hmma(float* c, const uint32_t* a, uint32_t b0, uint32_t b1){
  asm volatile(
    "mma.sync.aligned.m16n8k16.row.col.f32.bf16.bf16.f32 "
    "{%0,%1,%2,%3}, {%4,%5,%6,%7}, {%8,%9}, {%0,%1,%2,%3};"
    : "+f"(c[0]), "+f"(c[1]), "+f"(c[2]), "+f"(c[3])
    : "r"(a[0]), "r"(a[1]), "r"(a[2]), "r"(a[3]), "r"(b0), "r"(b1));
}
__device__ __forceinline__ void cp16z(uint32_t sdst, const void* gsrc, int srcsz){
  asm volatile("cp.async.cg.shared.global [%0], [%1], 16, %2;" :: "r"(sdst), "l"(gsrc), "r"(srcsz));
}
#define CP_COMMIT() asm volatile("cp.async.commit_group;" ::: "memory")
#define CP_WAIT1()  asm volatile("cp.async.wait_group 1;" ::: "memory")
#define PAIR_BAR(id) asm volatile("bar.sync %0, 64;" :: "r"(id) : "memory")

__device__ __forceinline__ void atomicMaxFloat(float* addr, float val){
  int* ai = (int*)addr;
  int old = *ai;
  while (true){
    float fo = __int_as_float(old);
    if (fo >= val) break;
    int assumed = old;
    old = atomicCAS(ai, assumed, __float_as_int(val));
    if (old == assumed) break;
  }
}

// ---------------- weight prep: pack W into mma B-fragment order -------------
// Per tap: u32 slot = (((wn*4+q)*2+pass)*2+quad)*128 + L*4 + r
//   n  = wn*32 + quad*16 + (r>>1)*8 + (L>>2)
//   kk = q*16 + (L&3)*2 + (r&1)*8        (kk in [0,64), even)
//   pass 0 = bf16-hi of W[kk..kk+1][n],  pass 1 = bf16 residual (lo)
__global__ void wprep_kernel(const float* __restrict__ W1,
                             const float* __restrict__ W2,
                             const float* __restrict__ Wk){
  int gid = blockIdx.x*256 + threadIdx.x;
  if (gid >= 5*KN*4096) return;
  int slot = gid & 4095;
  int tk = gid >> 12;
  int l = tk/KN, k = tk - l*KN;
  const float* Ws = (l==0)? W1 : (l==1)? W2 : (Wk + (size_t)(l-2)*KN*CH*CH);
  int r    = slot & 3;
  int L    = (slot >> 2) & 31;
  int rest = slot >> 7;
  int quad = rest & 1;
  int pass = (rest >> 1) & 1;
  int q    = (rest >> 2) & 3;
  int wn   = rest >> 4;
  int n  = wn*32 + quad*16 + (r>>1)*8 + (L>>2);
  int kk = q*16 + (L&3)*2 + (r&1)*8;
  float w0 = Ws[k*CH*CH + kk*CH + n];
  float w1 = Ws[k*CH*CH + (kk+1)*CH + n];
  __nv_bfloat16 b0, b1;
  if (pass == 0){
    b0 = __float2bfloat16(w0); b1 = __float2bfloat16(w1);
  } else {
    __nv_bfloat16 h0 = __float2bfloat16(w0), h1 = __float2bfloat16(w1);
    b0 = __float2bfloat16(w0 - __bfloat162float(h0));
    b1 = __float2bfloat16(w1 - __bfloat162float(h1));
  }
  g_wswz[tk*4096 + slot] =
      (uint32_t)__bfloat16_as_ushort(b0) | ((uint32_t)__bfloat16_as_ushort(b1) << 16);
}

// ---------------- fp32 -> (hi,lo) bf16 split of layer-0 input ---------------
__global__ void cvt_kernel(const float4* __restrict__ x,
                           __nv_bfloat162* __restrict__ ho,
                           __nv_bfloat162* __restrict__ lo){
  int i4 = blockIdx.x*256 + threadIdx.x;
  float4 v = x[i4];
  __nv_bfloat16 h0=__float2bfloat16(v.x), h1=__float2bfloat16(v.y),
                h2=__float2bfloat16(v.z), h3=__float2bfloat16(v.w);
  ho[2*i4]   = __halves2bfloat162(h0,h1);
  ho[2*i4+1] = __halves2bfloat162(h2,h3);
  lo[2*i4]   = __halves2bfloat162(__float2bfloat16(v.x-__bfloat162float(h0)),
                                  __float2bfloat16(v.y-__bfloat162float(h1)));
  lo[2*i4+1] = __halves2bfloat162(__float2bfloat16(v.z-__bfloat162float(h2)),
                                  __float2bfloat16(v.w-__bfloat162float(h3)));
}

// ---------------- HMMA gathered conv -----------------------------------------
// A: smem 128 rows x 256B ([hi|lo] chunks), double-buffered (64KB), pair-local sync.
// B: registers via LDG.128 from fragment-packed gmem (L2-hot), per-q double buffer.
// nbr: prefetched into smem once per block.
#define NBR_OFF 65536
#define SM_DYN (65536 + 13824 + 1024)

__device__ __forceinline__ void ldgB(const uint4* __restrict__ bw,
                                     int k, int q, int wn, int L, uint32_t* B){
  const uint4* p = bw + (size_t)k*1024 + (size_t)((wn*4 + q)*4)*32 + L;
#pragma unroll
  for (int pq = 0; pq < 4; pq++){
    uint4 v = __ldg(p + pq*32);
    B[pq*4+0] = v.x; B[pq*4+1] = v.y; B[pq*4+2] = v.z; B[pq*4+3] = v.w;
  }
}

__device__ __forceinline__ void fillA(
    int k, int buf, int t, uint32_t sb, const int* __restrict__ snbr,
    const __nv_bfloat16* __restrict__ hi, const __nv_bfloat16* __restrict__ lo)
{
  int r = (t>>6)*32 + ((t&63)>>1);   // pair-local rows
  int half = t & 1;
  int idx = snbr[r*KN + k];
  int sz = idx>=0 ? 16 : 0;
  int sidx = idx>=0 ? idx : 0;
  const char* asrc = (const char*)((half? lo: hi) + (size_t)sidx*CH);
  uint32_t abase = sb + buf*32768 + (uint32_t)r*256;
  int xr = r & 7;
#pragma unroll
  for (int j=0;j<8;j++){
    int c = half*8 + j;
    int sw = c ^ xr;
    cp16z(abase + sw*16, asrc + j*16, sz);
  }
}

__global__ void __launch_bounds__(256,2) conv_mma(
    const __nv_bfloat16* __restrict__ hi, const __nv_bfloat16* __restrict__ lo,
    const int* __restrict__ nbr, const uint32_t* __restrict__ bswz,
    float* __restrict__ dst)
{
  extern __shared__ char smraw[];
  char* sm = (char*)(((uintptr_t)smraw + 1023) & ~(uintptr_t)1023);
  const uint32_t sb = smem_u32(sm);
  int* snbr = (int*)(sm + NBR_OFF);
  __shared__ float sred[128];
  const uint4* bw = (const uint4*)bswz;

  const int t   = threadIdx.x;
  const int L   = t & 31;
  const int wid = t >> 5;
  const int wm  = wid >> 1;
  const int wn  = wid & 1;
  const int row0 = blockIdx.x * 128;
  const int barid = 1 + wm;

  if (t < 128) sred[t] = 0.f;

  // prefetch neighbor indices (contiguous slice)
  {
    const int* src = nbr + (size_t)row0*KN;
#pragma unroll
    for (int i = 0; i < 14; i++){
      int o = t + i*256;
      if (o < 128*KN) snbr[o] = src[o];
    }
  }
  __syncthreads();

  float acc[2][4][4];
#pragma unroll
  for (int s=0;s<2;s++)
#pragma unroll
    for (int nb=0;nb<4;nb++)
#pragma unroll
      for (int i=0;i<4;i++) acc[s][nb][i]=0.f;

  // lane-constant ldmatrix address pieces (A only)
  const int arow_l  = ((L>>3)&1)*8 + (L&7);
  const int a_clane = (L>>4);
  const int arow    = wm*32 + arow_l;
  const int axor    = arow & 7;

  fillA(0, 0, t, sb, snbr, hi, lo); CP_COMMIT();
  fillA(1, 1, t, sb, snbr, hi, lo); CP_COMMIT();

  uint32_t Bb0[16], Bb1[16];
  ldgB(bw, 0, 0, wn, L, Bb0);

  for (int k = 0; k < KN; k++){
    CP_WAIT1();
    PAIR_BAR(barid);

    const uint32_t Arow = sb + (k&1)*32768 + (uint32_t)arow*256;

#pragma unroll
    for (int q=0; q<4; q++){
      uint32_t* Bcur = (q&1) ? Bb1 : Bb0;
      uint32_t* Bnxt = (q&1) ? Bb0 : Bb1;
      // prefetch next q's B fragments
      if (q < 3) ldgB(bw, k, q+1, wn, L, Bnxt);
      else       ldgB(bw, (k+1<KN)?(k+1):k, 0, wn, L, Bnxt);

      const int c_hi = q*2;
      const int c_lo = c_hi + 8;

      uint32_t Ah0[4], Ah1[4], T0[4], T1[4];
      uint32_t ah = Arow + (uint32_t)(((c_hi + a_clane) ^ axor)*16);
      ldsm_x4(ah, Ah0);
      ldsm_x4(ah + 16*256, Ah1);
      uint32_t al = Arow + (uint32_t)(((c_lo + a_clane) ^ axor)*16);
      ldsm_x4(al, T0);
      ldsm_x4(al + 16*256, T1);

      // pass 0: A_hi x B_hi
      hmma(acc[0][0], Ah0, Bcur[0],  Bcur[1]);
      hmma(acc[0][1], Ah0, Bcur[2],  Bcur[3]);
      hmma(acc[0][2], Ah0, Bcur[4],  Bcur[5]);
      hmma(acc[0][3], Ah0, Bcur[6],  Bcur[7]);
      hmma(acc[1][0], Ah1, Bcur[0],  Bcur[1]);
      hmma(acc[1][1], Ah1, Bcur[2],  Bcur[3]);
      hmma(acc[1][2], Ah1, Bcur[4],  Bcur[5]);
      hmma(acc[1][3], Ah1, Bcur[6],  Bcur[7]);
      // pass 1: A_lo x B_hi
      hmma(acc[0][0], T0,  Bcur[0],  Bcur[1]);
      hmma(acc[0][1], T0,  Bcur[2],  Bcur[3]);
      hmma(acc[0][2], T0,  Bcur[4],  Bcur[5]);
      hmma(acc[0][3], T0,  Bcur[6],  Bcur[7]);
      hmma(acc[1][0], T1,  Bcur[0],  Bcur[1]);
      hmma(acc[1][1], T1,  Bcur[2],  Bcur[3]);
      hmma(acc[1][2], T1,  Bcur[4],  Bcur[5]);
      hmma(acc[1][3], T1,  Bcur[6],  Bcur[7]);
      // pass 2: A_hi x B_lo
      hmma(acc[0][0], Ah0, Bcur[8],  Bcur[9]);
      hmma(acc[0][1], Ah0, Bcur[10], Bcur[11]);
      hmma(acc[0][2], Ah0, Bcur[12], Bcur[13]);
      hmma(acc[0][3], Ah0, Bcur[14], Bcur[15]);
      hmma(acc[1][0], Ah1, Bcur[8],  Bcur[9]);
      hmma(acc[1][1], Ah1, Bcur[10], Bcur[11]);
      hmma(acc[1][2], Ah1, Bcur[12], Bcur[13]);
      hmma(acc[1][3], Ah1, Bcur[14], Bcur[15]);
    }
    PAIR_BAR(barid);
    if (k+2 < KN) fillA(k+2, k&1, t, sb, snbr, hi, lo);
    CP_COMMIT();
  }

  // ---- epilogue: stores + fused per-channel stats
#pragma unroll
  for (int s=0;s<2;s++){
    int r = row0 + wm*32 + s*16 + (L>>2);
#pragma unroll
    for (int nb=0;nb<4;nb++){
      int col = wn*32 + nb*8 + (L&3)*2;
      float* c = acc[s][nb];
      *(float2*)&dst[(size_t)r*CH + col]     = make_float2(c[0], c[1]);
      *(float2*)&dst[(size_t)(r+8)*CH + col] = make_float2(c[2], c[3]);
    }
  }
#pragma unroll
  for (int nb=0;nb<4;nb++){
    float sc0=0.f, sc1=0.f, qc0=0.f, qc1=0.f;
#pragma unroll
    for (int s=0;s<2;s++){
      float* c = acc[s][nb];
      sc0 += c[0]+c[2]; qc0 += c[0]*c[0]+c[2]*c[2];
      sc1 += c[1]+c[3]; qc1 += c[1]*c[1]+c[3]*c[3];
    }
#pragma unroll
    for (int m=4;m<32;m<<=1){
      sc0 += __shfl_xor_sync(0xFFFFFFFFu, sc0, m);
      sc1 += __shfl_xor_sync(0xFFFFFFFFu, sc1, m);
      qc0 += __shfl_xor_sync(0xFFFFFFFFu, qc0, m);
      qc1 += __shfl_xor_sync(0xFFFFFFFFu, qc1, m);
    }
    if (L < 4){
      int col = wn*32 + nb*8 + L*2;
      atomicAdd(&sred[col],    sc0); atomicAdd(&sred[col+1],    sc1);
      atomicAdd(&sred[64+col], qc0); atomicAdd(&sred[64+col+1], qc1);
    }
  }
  __syncthreads();
  if (t < 64){
    atomicAdd(&g_sum[t],   sred[t]);
    atomicAdd(&g_sumsq[t], sred[64+t]);
  }
}

// ---------------- stats clear ----------------------------------------------
__global__ void clear_stats_kernel(){
  int t = threadIdx.x; if (t < CH){ g_sum[t]=0.f; g_sumsq[t]=0.f; }
}

// ---------------- BN apply + emit fp32 and/or bf16 hi/lo --------------------
__global__ void bn2_kernel(const float* __restrict__ x, const float* __restrict__ gg,
                           const float* __restrict__ bb, int relu,
                           float* __restrict__ fout,
                           __nv_bfloat162* __restrict__ ho,
                           __nv_bfloat162* __restrict__ lo){
  __shared__ float sc[64], bi[64];
  int t = threadIdx.x;
  if (t < 64){
    float m = g_sum[t]*(1.f/NPTS);
    float v = g_sumsq[t]*(1.f/NPTS) - m*m;
    float s = rsqrtf(v + 1e-5f) * gg[t];
    sc[t] = s; bi[t] = bb[t] - m*s;
  }
  __syncthreads();
  int i4 = blockIdx.x*256 + t;
  float4 v = ((const float4*)x)[i4];
  int c = (i4 & 15)*4;
  v.x = v.x*sc[c]+bi[c];     v.y = v.y*sc[c+1]+bi[c+1];
  v.z = v.z*sc[c+2]+bi[c+2]; v.w = v.w*sc[c+3]+bi[c+3];
  if (relu){ v.x=fmaxf(v.x,0.f); v.y=fmaxf(v.y,0.f); v.z=fmaxf(v.z,0.f); v.w=fmaxf(v.w,0.f); }
  if (fout) ((float4*)fout)[i4] = v;
  if (ho){
    __nv_bfloat16 h0=__float2bfloat16(v.x), h1=__float2bfloat16(v.y),
                  h2=__float2bfloat16(v.z), h3=__float2bfloat16(v.w);
    ho[2*i4]   = __halves2bfloat162(h0,h1);
    ho[2*i4+1] = __halves2bfloat162(h2,h3);
    lo[2*i4]   = __halves2bfloat162(__float2bfloat16(v.x-__bfloat162float(h0)),
                                    __float2bfloat16(v.y-__bfloat162float(h1)));
    lo[2*i4+1] = __halves2bfloat162(__float2bfloat16(v.z-__bfloat162float(h2)),
                                    __float2bfloat16(v.w-__bfloat162float(h3)));
  }
}

// ---------------- segment sum/max over batches (B=2), 192 channels ---------
__global__ void clear_seg_kernel(){
  int t = threadIdx.x; if (t < NB*CAQ){ g_segsum[t]=0.f; g_segmax[t]=-FLT_MAX; }
}
__global__ void seg_kernel(const int* __restrict__ bidx){
  int j = threadIdx.x;
  const float* kxp = (j<64)? g_kx0 : ((j<128)? g_kx1 : g_kx2);
  int c = j & 63;
  int n0 = blockIdx.x*400, n1 = n0+400;
  float s0=0.f, s1=0.f, m0=-FLT_MAX, m1=-FLT_MAX;
  for (int n=n0;n<n1;n++){
    float v = kxp[n*CH + c];
    if (bidx[n]==0){ s0+=v; m0=fmaxf(m0,v); } else { s1+=v; m1=fmaxf(m1,v); }
  }
  atomicAdd(&g_segsum[j], s0);
  atomicAdd(&g_segsum[CAQ+j], s1);
  atomicMaxFloat(&g_segmax[j], m0);
  atomicMaxFloat(&g_segmax[CAQ+j], m1);
}

// ---------------- tiny FC + sigmoid attention ------------------------------
__global__ void fc_kernel(const int* __restrict__ bidx,
    const float* __restrict__ w1, const float* __restrict__ b1,
    const float* __restrict__ w2, const float* __restrict__ b2,
    const float* __restrict__ ksw)
{
  __shared__ float ha[NB][HID], hm[NB][HID];
  __shared__ int red[256];
  __shared__ int scnt[NB];
  int t = threadIdx.x;
  int c0 = 0;
  for (int n=t; n<NPTS; n+=256) c0 += (bidx[n]==0);
  red[t]=c0; __syncthreads();
  for (int s=128;s>0;s>>=1){ if (t<s) red[t]+=red[t+s]; __syncthreads(); }
  if (t==0){ scnt[0]=red[0]; scnt[1]=NPTS-red[0]; }
  __syncthreads();
  if (t<48){
    int which = t/24;
    int b  = (t/12)%2;
    int tt = t%12;
    float s = b1[tt];
    float inv = 1.f/(float)scnt[b];
    for (int j=0;j<CAQ;j++){
      float z = which ? g_segmax[b*CAQ+j] : g_segsum[b*CAQ+j]*inv;
      s += z * w1[j*HID+tt];
    }
    s = fmaxf(s,0.f);
    if (which) hm[b][tt]=s; else ha[b][tt]=s;
  }
  __syncthreads();
  for (int o=t; o<NB*CAQ; o+=256){
    int b=o/CAQ, j=o%CAQ;
    float sa=b2[j], sm=b2[j];
    for (int tt=0;tt<HID;tt++){ sa += ha[b][tt]*w2[tt*CAQ+j]; sm += hm[b][tt]*w2[tt*CAQ+j]; }
    float s = sa+sm;
    g_att[o] = 1.f/(1.f+expf(-s));
  }
  if (t<NXX) g_wsig[t] = 1.f/(1.f+expf(-ksw[t]));
}

// ---------------- fusion epilogue ------------------------------------------
__device__ __forceinline__ float kx_read(int sel, int off){
  return sel==0 ? g_kx0[off] : (sel==1 ? g_kx1[off] : g_kx2[off]);
}
__global__ void final_kernel(const float* __restrict__ feats,
                             const int* __restrict__ bidx,
                             float* __restrict__ out){
  int i = blockIdx.x*256 + threadIdx.x;
  int n = i >> 6, c = i & 63;
  int b = bidx[n];
  float acc = feats[i];
#pragma unroll
  for (int ii=0; ii<NXX; ii++){
    int j = 3*c + ii;
    int sel = j >> 6, col = j & 63;
    float xj  = kx_read(sel, n*CH + col);
    float kxi = kx_read(ii, i);
    acc += g_wsig[ii] * (kxi + xj * g_att[b*CAQ + j]);
  }
  out[i] = fmaxf(acc, 0.f);
}

// ---------------- launch ----------------------------------------------------
extern "C" void kernel_launch(void* const* d_in, const int* in_sizes, int n_in,
                              void* d_out, int out_size){
  (void)in_sizes; (void)n_in; (void)out_size;
  const float* feats=(const float*)d_in[0];
  const int*   bidx =(const int*)d_in[1];
  const int*   nbr  =(const int*)d_in[2];
  const float* W1 =(const float*)d_in[3];
  const float* g1 =(const float*)d_in[4];
  const float* b1 =(const float*)d_in[5];
  const float* W2 =(const float*)d_in[6];
  const float* g2 =(const float*)d_in[7];
  const float* b2 =(const float*)d_in[8];
  const float* Wk =(const float*)d_in[9];
  const float* gk =(const float*)d_in[10];
  const float* bk =(const float*)d_in[11];
  const float* fc1w=(const float*)d_in[12];
  const float* fc1b=(const float*)d_in[13];
  const float* fc2w=(const float*)d_in[14];
  const float* fc2b=(const float*)d_in[15];
  const float* ksw =(const float*)d_in[16];
  float* out=(float*)d_out;

  float *pConv,*pk0,*pk1,*pk2;
  __nv_bfloat162 *pHiA,*pLoA,*pHiB,*pLoB;
  uint32_t* pW;
  cudaGetSymbolAddress((void**)&pConv, g_conv);
  cudaGetSymbolAddress((void**)&pk0, g_kx0);
  cudaGetSymbolAddress((void**)&pk1, g_kx1);
  cudaGetSymbolAddress((void**)&pk2, g_kx2);
  cudaGetSymbolAddress((void**)&pHiA, g_hiA);
  cudaGetSymbolAddress((void**)&pLoA, g_loA);
  cudaGetSymbolAddress((void**)&pHiB, g_hiB);
  cudaGetSymbolAddress((void**)&pLoB, g_loB);
  cudaGetSymbolAddress((void**)&pW,  g_wswz);

  cudaFuncSetAttribute(conv_mma, cudaFuncAttributeMaxDynamicSharedMemorySize, SM_DYN);

  wprep_kernel<<<(5*KN*4096 + 255)/256, 256>>>(W1, W2, Wk);
  cvt_kernel<<<NPTS*CH/4/256, 256>>>((const float4*)feats, pHiA, pLoA);

  struct Step {
    const __nv_bfloat16 *hi, *lo; const uint32_t* bw;
    const float *g, *b; int relu;
    float* fout; __nv_bfloat162 *ho, *loo;
  };
  Step steps[5] = {
    {(const __nv_bfloat16*)pHiA,(const __nv_bfloat16*)pLoA, pW + 0*KN*4096, g1,      b1,      1, nullptr, pHiB, pLoB},
    {(const __nv_bfloat16*)pHiB,(const __nv_bfloat16*)pLoB, pW + 1*KN*4096, g2,      b2,      0, nullptr, pHiA, pLoA},
    {(const __nv_bfloat16*)pHiA,(const __nv_bfloat16*)pLoA, pW + 2*KN*4096, gk,      bk,      1, pk0,     pHiB, pLoB},
    {(const __nv_bfloat16*)pHiB,(const __nv_bfloat16*)pLoB, pW + 3*KN*4096, gk+CH,   bk+CH,   1, pk1,     pHiA, pLoA},
    {(const __nv_bfloat16*)pHiA,(const __nv_bfloat16*)pLoA, pW + 4*KN*4096, gk+2*CH, bk+2*CH, 1, pk2,     nullptr, nullptr},
  };
  for (int s=0;s<5;s++){
    clear_stats_kernel<<<1,64>>>();
    conv_mma<<<NPTS/128, 256, SM_DYN>>>(steps[s].hi, steps[s].lo, nbr, steps[s].bw, pConv);
    bn2_kernel<<<NPTS*CH/4/256, 256>>>(pConv, steps[s].g, steps[s].b, steps[s].relu,
                                       steps[s].fout, steps[s].ho, steps[s].loo);
  }
  clear_seg_kernel<<<1, NB*CAQ>>>();
  seg_kernel<<<200, CAQ>>>(bidx);
  fc_kernel<<<1,256>>>(bidx, fc1w, fc1b, fc2w, fc2b, ksw);
  final_kernel<<<(NPTS*CH)/256, 256>>>(feats, bidx, out);
}

// round 6
// speedup vs baseline: 2.6004x; 1.0654x over previous
#include <cuda_runtime.h>
#include <cuda_bf16.h>
#include <math.h>
#include <float.h>
#include <stdint.h>

#define NPTS 80000
#define CH   64
#define KN   27
#define NB   2
#define NXX  3
#define CAQ  192
#define HID  12

// ---------------- scratch (device globals; no allocation allowed) ----------
__device__ float g_conv[NPTS*CH];
__device__ float g_kx0[NPTS*CH];
__device__ float g_kx1[NPTS*CH];
__device__ float g_kx2[NPTS*CH];
__device__ __nv_bfloat162 g_hiA[NPTS*CH/2];
__device__ __nv_bfloat162 g_loA[NPTS*CH/2];
__device__ __nv_bfloat162 g_hiB[NPTS*CH/2];
__device__ __nv_bfloat162 g_loB[NPTS*CH/2];
__device__ uint32_t g_wswz[5*KN*4096];      // B tiles packed in mma fragment order (16KB/tap)
__device__ float g_sum[CH], g_sumsq[CH];
__device__ float g_segsum[NB*CAQ], g_segmax[NB*CAQ], g_att[NB*CAQ], g_wsig[NXX];

// ---------------- helpers ----------------------------------------------------
__device__ __forceinline__ uint32_t smem_u32(const void* p){
  uint32_t a;
  asm("{ .reg .u64 t; cvta.to.shared.u64 t, %1; cvt.u32.u64 %0, t; }" : "=r"(a) : "l"(p));
  return a;
}
__device__ __forceinline__ void ldsm_x4(uint32_t addr, uint32_t* r){
  asm volatile("ldmatrix.sync.aligned.m8n8.x4.shared.b16 {%0,%1,%2,%3}, [%4];"
    : "=r"(r[0]),"=r"(r[1]),"=r"(r[2]),"=r"(r[3]) : "r"(addr));
}
__device__ __forceinline__ void hmma(float* c, const uint32_t* a, uint32_t b0, uint32_t b1){
  asm volatile(
    "mma.sync.aligned.m16n8k16.row.col.f32.bf16.bf16.f32 "
    "{%0,%1,%2,%3}, {%4,%5,%6,%7}, {%8,%9}, {%0,%1,%2,%3};"
    : "+f"(c[0]), "+f"(c[1]), "+f"(c[2]), "+f"(c[3])
    : "r"(a[0]), "r"(a[1]), "r"(a[2]), "r"(a[3]), "r"(b0), "r"(b1));
}
__device__ __forceinline__ void cp16z(uint32_t sdst, const void* gsrc, int srcsz){
  asm volatile("cp.async.cg.shared.global [%0], [%1], 16, %2;" :: "r"(sdst), "l"(gsrc), "r"(srcsz));
}
#define CP_COMMIT() asm volatile("cp.async.commit_group;" ::: "memory")
#define CP_WAIT1()  asm volatile("cp.async.wait_group 1;" ::: "memory")
#define PAIR_BAR(id) asm volatile("bar.sync %0, 64;" :: "r"(id) : "memory")

__device__ __forceinline__ void atomicMaxFloat(float* addr, float val){
  int* ai = (int*)addr;
  int old = *ai;
  while (true){
    float fo = __int_as_float(old);
    if (fo >= val) break;
    int assumed = old;
    old = atomicCAS(ai, assumed, __float_as_int(val));
    if (old == assumed) break;
  }
}

// ---------------- weight prep: pack W into mma B-fragment order -------------
__global__ void wprep_kernel(const float* __restrict__ W1,
                             const float* __restrict__ W2,
                             const float* __restrict__ Wk){
  int gid = blockIdx.x*256 + threadIdx.x;
  if (gid >= 5*KN*4096) return;
  int slot = gid & 4095;
  int tk = gid >> 12;
  int l = tk/KN, k = tk - l*KN;
  const float* Ws = (l==0)? W1 : (l==1)? W2 : (Wk + (size_t)(l-2)*KN*CH*CH);
  int r    = slot & 3;
  int L    = (slot >> 2) & 31;
  int rest = slot >> 7;
  int quad = rest & 1;
  int pass = (rest >> 1) & 1;
  int q    = (rest >> 2) & 3;
  int wn   = rest >> 4;
  int n  = wn*32 + quad*16 + (r>>1)*8 + (L>>2);
  int kk = q*16 + (L&3)*2 + (r&1)*8;
  float w0 = Ws[k*CH*CH + kk*CH + n];
  float w1 = Ws[k*CH*CH + (kk+1)*CH + n];
  __nv_bfloat16 b0, b1;
  if (pass == 0){
    b0 = __float2bfloat16(w0); b1 = __float2bfloat16(w1);
  } else {
    __nv_bfloat16 h0 = __float2bfloat16(w0), h1 = __float2bfloat16(w1);
    b0 = __float2bfloat16(w0 - __bfloat162float(h0));
    b1 = __float2bfloat16(w1 - __bfloat162float(h1));
  }
  g_wswz[tk*4096 + slot] =
      (uint32_t)__bfloat16_as_ushort(b0) | ((uint32_t)__bfloat16_as_ushort(b1) << 16);
}

// ---------------- fp32 -> (hi,lo) bf16 split of layer-0 input ---------------
__global__ void cvt_kernel(const float4* __restrict__ x,
                           __nv_bfloat162* __restrict__ ho,
                           __nv_bfloat162* __restrict__ lo){
  int i4 = blockIdx.x*256 + threadIdx.x;
  float4 v = x[i4];
  __nv_bfloat16 h0=__float2bfloat16(v.x), h1=__float2bfloat16(v.y),
                h2=__float2bfloat16(v.z), h3=__float2bfloat16(v.w);
  ho[2*i4]   = __halves2bfloat162(h0,h1);
  ho[2*i4+1] = __halves2bfloat162(h2,h3);
  lo[2*i4]   = __halves2bfloat162(__float2bfloat16(v.x-__bfloat162float(h0)),
                                  __float2bfloat16(v.y-__bfloat162float(h1)));
  lo[2*i4+1] = __halves2bfloat162(__float2bfloat16(v.z-__bfloat162float(h2)),
                                  __float2bfloat16(v.w-__bfloat162float(h3)));
}

// ---------------- HMMA gathered conv -----------------------------------------
// A: smem 128 rows x 256B ([hi|lo] chunks), TRIPLE-buffered (96KB), 1 pair-bar/tap.
// B: registers via LDG.128 from fragment-packed gmem (L2-hot), per-q double buffer.
// nbr: prefetched into smem once per block.
#define NBR_OFF 98304
#define SM_DYN (98304 + 13824 + 1024)

__device__ __forceinline__ void ldgB(const uint4* __restrict__ bw,
                                     int k, int q, int wn, int L, uint32_t* B){
  const uint4* p = bw + (size_t)k*1024 + (size_t)((wn*4 + q)*4)*32 + L;
#pragma unroll
  for (int pq = 0; pq < 4; pq++){
    uint4 v = __ldg(p + pq*32);
    B[pq*4+0] = v.x; B[pq*4+1] = v.y; B[pq*4+2] = v.z; B[pq*4+3] = v.w;
  }
}

__device__ __forceinline__ void fillA(
    int k, int buf, int t, uint32_t sb, const int* __restrict__ snbr,
    const __nv_bfloat16* __restrict__ hi, const __nv_bfloat16* __restrict__ lo)
{
  int r = (t>>6)*32 + ((t&63)>>1);   // pair-local rows
  int half = t & 1;
  int idx = snbr[r*KN + k];
  int sz = idx>=0 ? 16 : 0;
  int sidx = idx>=0 ? idx : 0;
  const char* asrc = (const char*)((half? lo: hi) + (size_t)sidx*CH);
  uint32_t abase = sb + buf*32768 + (uint32_t)r*256;
  int xr = r & 7;
#pragma unroll
  for (int j=0;j<8;j++){
    int c = half*8 + j;
    int sw = c ^ xr;
    cp16z(abase + sw*16, asrc + j*16, sz);
  }
}

__global__ void __launch_bounds__(256,2) conv_mma(
    const __nv_bfloat16* __restrict__ hi, const __nv_bfloat16* __restrict__ lo,
    const int* __restrict__ nbr, const uint32_t* __restrict__ bswz,
    float* __restrict__ dst)
{
  extern __shared__ char smraw[];
  char* sm = (char*)(((uintptr_t)smraw + 1023) & ~(uintptr_t)1023);
  const uint32_t sb = smem_u32(sm);
  int* snbr = (int*)(sm + NBR_OFF);
  __shared__ float sred[128];
  const uint4* bw = (const uint4*)bswz;

  const int t   = threadIdx.x;
  const int L   = t & 31;
  const int wid = t >> 5;
  const int wm  = wid >> 1;
  const int wn  = wid & 1;
  const int row0 = blockIdx.x * 128;
  const int barid = 1 + wm;

  if (t < 128) sred[t] = 0.f;

  // prefetch neighbor indices (contiguous slice)
  {
    const int* src = nbr + (size_t)row0*KN;
#pragma unroll
    for (int i = 0; i < 14; i++){
      int o = t + i*256;
      if (o < 128*KN) snbr[o] = src[o];
    }
  }
  __syncthreads();

  float acc[2][4][4];
#pragma unroll
  for (int s=0;s<2;s++)
#pragma unroll
    for (int nb=0;nb<4;nb++)
#pragma unroll
      for (int i=0;i<4;i++) acc[s][nb][i]=0.f;

  // lane-constant ldmatrix address pieces (A only)
  const int arow_l  = ((L>>3)&1)*8 + (L&7);
  const int a_clane = (L>>4);
  const int arow    = wm*32 + arow_l;
  const int axor    = arow & 7;

  fillA(0, 0, t, sb, snbr, hi, lo); CP_COMMIT();
  fillA(1, 1, t, sb, snbr, hi, lo); CP_COMMIT();

  uint32_t Bb0[16], Bb1[16];
  ldgB(bw, 0, 0, wn, L, Bb0);

  int buf  = 0;   // buffer for tap k
  int bufN = 2;   // buffer to fill with tap k+2

  for (int k = 0; k < KN; k++){
    CP_WAIT1();
    PAIR_BAR(barid);

    // fill tap k+2 now (writes buffer consumed at tap k-1; bar above proves
    // the partner warp is done with it). ~2 taps of slack before its wait.
    if (k+2 < KN) fillA(k+2, bufN, t, sb, snbr, hi, lo);
    CP_COMMIT();

    const uint32_t Arow = sb + (uint32_t)buf*32768 + (uint32_t)arow*256;

#pragma unroll
    for (int q=0; q<4; q++){
      uint32_t* Bcur = (q&1) ? Bb1 : Bb0;
      uint32_t* Bnxt = (q&1) ? Bb0 : Bb1;
      if (q < 3) ldgB(bw, k, q+1, wn, L, Bnxt);
      else       ldgB(bw, (k+1<KN)?(k+1):k, 0, wn, L, Bnxt);

      const int c_hi = q*2;
      const int c_lo = c_hi + 8;

      uint32_t Ah0[4], Ah1[4], T0[4], T1[4];
      uint32_t ah = Arow + (uint32_t)(((c_hi + a_clane) ^ axor)*16);
      ldsm_x4(ah, Ah0);
      ldsm_x4(ah + 16*256, Ah1);
      uint32_t al = Arow + (uint32_t)(((c_lo + a_clane) ^ axor)*16);
      ldsm_x4(al, T0);
      ldsm_x4(al + 16*256, T1);

      // pass 0: A_hi x B_hi
      hmma(acc[0][0], Ah0, Bcur[0],  Bcur[1]);
      hmma(acc[0][1], Ah0, Bcur[2],  Bcur[3]);
      hmma(acc[0][2], Ah0, Bcur[4],  Bcur[5]);
      hmma(acc[0][3], Ah0, Bcur[6],  Bcur[7]);
      hmma(acc[1][0], Ah1, Bcur[0],  Bcur[1]);
      hmma(acc[1][1], Ah1, Bcur[2],  Bcur[3]);
      hmma(acc[1][2], Ah1, Bcur[4],  Bcur[5]);
      hmma(acc[1][3], Ah1, Bcur[6],  Bcur[7]);
      // pass 1: A_lo x B_hi
      hmma(acc[0][0], T0,  Bcur[0],  Bcur[1]);
      hmma(acc[0][1], T0,  Bcur[2],  Bcur[3]);
      hmma(acc[0][2], T0,  Bcur[4],  Bcur[5]);
      hmma(acc[0][3], T0,  Bcur[6],  Bcur[7]);
      hmma(acc[1][0], T1,  Bcur[0],  Bcur[1]);
      hmma(acc[1][1], T1,  Bcur[2],  Bcur[3]);
      hmma(acc[1][2], T1,  Bcur[4],  Bcur[5]);
      hmma(acc[1][3], T1,  Bcur[6],  Bcur[7]);
      // pass 2: A_hi x B_lo
      hmma(acc[0][0], Ah0, Bcur[8],  Bcur[9]);
      hmma(acc[0][1], Ah0, Bcur[10], Bcur[11]);
      hmma(acc[0][2], Ah0, Bcur[12], Bcur[13]);
      hmma(acc[0][3], Ah0, Bcur[14], Bcur[15]);
      hmma(acc[1][0], Ah1, Bcur[8],  Bcur[9]);
      hmma(acc[1][1], Ah1, Bcur[10], Bcur[11]);
      hmma(acc[1][2], Ah1, Bcur[12], Bcur[13]);
      hmma(acc[1][3], Ah1, Bcur[14], Bcur[15]);
    }
    buf  = (buf  == 2) ? 0 : buf+1;
    bufN = (bufN == 2) ? 0 : bufN+1;
  }

  // ---- epilogue: stores + fused per-channel stats
#pragma unroll
  for (int s=0;s<2;s++){
    int r = row0 + wm*32 + s*16 + (L>>2);
#pragma unroll
    for (int nb=0;nb<4;nb++){
      int col = wn*32 + nb*8 + (L&3)*2;
      float* c = acc[s][nb];
      *(float2*)&dst[(size_t)r*CH + col]     = make_float2(c[0], c[1]);
      *(float2*)&dst[(size_t)(r+8)*CH + col] = make_float2(c[2], c[3]);
    }
  }
#pragma unroll
  for (int nb=0;nb<4;nb++){
    float sc0=0.f, sc1=0.f, qc0=0.f, qc1=0.f;
#pragma unroll
    for (int s=0;s<2;s++){
      float* c = acc[s][nb];
      sc0 += c[0]+c[2]; qc0 += c[0]*c[0]+c[2]*c[2];
      sc1 += c[1]+c[3]; qc1 += c[1]*c[1]+c[3]*c[3];
    }
#pragma unroll
    for (int m=4;m<32;m<<=1){
      sc0 += __shfl_xor_sync(0xFFFFFFFFu, sc0, m);
      sc1 += __shfl_xor_sync(0xFFFFFFFFu, sc1, m);
      qc0 += __shfl_xor_sync(0xFFFFFFFFu, qc0, m);
      qc1 += __shfl_xor_sync(0xFFFFFFFFu, qc1, m);
    }
    if (L < 4){
      int col = wn*32 + nb*8 + L*2;
      atomicAdd(&sred[col],    sc0); atomicAdd(&sred[col+1],    sc1);
      atomicAdd(&sred[64+col], qc0); atomicAdd(&sred[64+col+1], qc1);
    }
  }
  __syncthreads();
  if (t < 64){
    atomicAdd(&g_sum[t],   sred[t]);
    atomicAdd(&g_sumsq[t], sred[64+t]);
  }
}

// ---------------- stats clear ----------------------------------------------
__global__ void clear_stats_kernel(){
  int t = threadIdx.x; if (t < CH){ g_sum[t]=0.f; g_sumsq[t]=0.f; }
}

// ---------------- BN apply + emit fp32 and/or bf16 hi/lo --------------------
__global__ void bn2_kernel(const float* __restrict__ x, const float* __restrict__ gg,
                           const float* __restrict__ bb, int relu,
                           float* __restrict__ fout,
                           __nv_bfloat162* __restrict__ ho,
                           __nv_bfloat162* __restrict__ lo){
  __shared__ float sc[64], bi[64];
  int t = threadIdx.x;
  if (t < 64){
    float m = g_sum[t]*(1.f/NPTS);
    float v = g_sumsq[t]*(1.f/NPTS) - m*m;
    float s = rsqrtf(v + 1e-5f) * gg[t];
    sc[t] = s; bi[t] = bb[t] - m*s;
  }
  __syncthreads();
  int i4 = blockIdx.x*256 + t;
  float4 v = ((const float4*)x)[i4];
  int c = (i4 & 15)*4;
  v.x = v.x*sc[c]+bi[c];     v.y = v.y*sc[c+1]+bi[c+1];
  v.z = v.z*sc[c+2]+bi[c+2]; v.w = v.w*sc[c+3]+bi[c+3];
  if (relu){ v.x=fmaxf(v.x,0.f); v.y=fmaxf(v.y,0.f); v.z=fmaxf(v.z,0.f); v.w=fmaxf(v.w,0.f); }
  if (fout) ((float4*)fout)[i4] = v;
  if (ho){
    __nv_bfloat16 h0=__float2bfloat16(v.x), h1=__float2bfloat16(v.y),
                  h2=__float2bfloat16(v.z), h3=__float2bfloat16(v.w);
    ho[2*i4]   = __halves2bfloat162(h0,h1);
    ho[2*i4+1] = __halves2bfloat162(h2,h3);
    lo[2*i4]   = __halves2bfloat162(__float2bfloat16(v.x-__bfloat162float(h0)),
                                    __float2bfloat16(v.y-__bfloat162float(h1)));
    lo[2*i4+1] = __halves2bfloat162(__float2bfloat16(v.z-__bfloat162float(h2)),
                                    __float2bfloat16(v.w-__bfloat162float(h3)));
  }
}

// ---------------- segment sum/max over batches (B=2), 192 channels ---------
__global__ void clear_seg_kernel(){
  int t = threadIdx.x; if (t < NB*CAQ){ g_segsum[t]=0.f; g_segmax[t]=-FLT_MAX; }
}
__global__ void seg_kernel(const int* __restrict__ bidx){
  int j = threadIdx.x;
  const float* kxp = (j<64)? g_kx0 : ((j<128)? g_kx1 : g_kx2);
  int c = j & 63;
  int n0 = blockIdx.x*400, n1 = n0+400;
  float s0=0.f, s1=0.f, m0=-FLT_MAX, m1=-FLT_MAX;
  for (int n=n0;n<n1;n++){
    float v = kxp[n*CH + c];
    if (bidx[n]==0){ s0+=v; m0=fmaxf(m0,v); } else { s1+=v; m1=fmaxf(m1,v); }
  }
  atomicAdd(&g_segsum[j], s0);
  atomicAdd(&g_segsum[CAQ+j], s1);
  atomicMaxFloat(&g_segmax[j], m0);
  atomicMaxFloat(&g_segmax[CAQ+j], m1);
}

// ---------------- tiny FC + sigmoid attention ------------------------------
__global__ void fc_kernel(const int* __restrict__ bidx,
    const float* __restrict__ w1, const float* __restrict__ b1,
    const float* __restrict__ w2, const float* __restrict__ b2,
    const float* __restrict__ ksw)
{
  __shared__ float ha[NB][HID], hm[NB][HID];
  __shared__ int red[256];
  __shared__ int scnt[NB];
  int t = threadIdx.x;
  int c0 = 0;
  for (int n=t; n<NPTS; n+=256) c0 += (bidx[n]==0);
  red[t]=c0; __syncthreads();
  for (int s=128;s>0;s>>=1){ if (t<s) red[t]+=red[t+s]; __syncthreads(); }
  if (t==0){ scnt[0]=red[0]; scnt[1]=NPTS-red[0]; }
  __syncthreads();
  if (t<48){
    int which = t/24;
    int b  = (t/12)%2;
    int tt = t%12;
    float s = b1[tt];
    float inv = 1.f/(float)scnt[b];
    for (int j=0;j<CAQ;j++){
      float z = which ? g_segmax[b*CAQ+j] : g_segsum[b*CAQ+j]*inv;
      s += z * w1[j*HID+tt];
    }
    s = fmaxf(s,0.f);
    if (which) hm[b][tt]=s; else ha[b][tt]=s;
  }
  __syncthreads();
  for (int o=t; o<NB*CAQ; o+=256){
    int b=o/CAQ, j=o%CAQ;
    float sa=b2[j], sm=b2[j];
    for (int tt=0;tt<HID;tt++){ sa += ha[b][tt]*w2[tt*CAQ+j]; sm += hm[b][tt]*w2[tt*CAQ+j]; }
    float s = sa+sm;
    g_att[o] = 1.f/(1.f+expf(-s));
  }
  if (t<NXX) g_wsig[t] = 1.f/(1.f+expf(-ksw[t]));
}

// ---------------- fusion epilogue ------------------------------------------
__device__ __forceinline__ float kx_read(int sel, int off){
  return sel==0 ? g_kx0[off] : (sel==1 ? g_kx1[off] : g_kx2[off]);
}
__global__ void final_kernel(const float* __restrict__ feats,
                             const int* __restrict__ bidx,
                             float* __restrict__ out){
  int i = blockIdx.x*256 + threadIdx.x;
  int n = i >> 6, c = i & 63;
  int b = bidx[n];
  float acc = feats[i];
#pragma unroll
  for (int ii=0; ii<NXX; ii++){
    int j = 3*c + ii;
    int sel = j >> 6, col = j & 63;
    float xj  = kx_read(sel, n*CH + col);
    float kxi = kx_read(ii, i);
    acc += g_wsig[ii] * (kxi + xj * g_att[b*CAQ + j]);
  }
  out[i] = fmaxf(acc, 0.f);
}

// ---------------- launch ----------------------------------------------------
extern "C" void kernel_launch(void* const* d_in, const int* in_sizes, int n_in,
                              void* d_out, int out_size){
  (void)in_sizes; (void)n_in; (void)out_size;
  const float* feats=(const float*)d_in[0];
  const int*   bidx =(const int*)d_in[1];
  const int*   nbr  =(const int*)d_in[2];
  const float* W1 =(const float*)d_in[3];
  const float* g1 =(const float*)d_in[4];
  const float* b1 =(const float*)d_in[5];
  const float* W2 =(const float*)d_in[6];
  const float* g2 =(const float*)d_in[7];
  const float* b2 =(const float*)d_in[8];
  const float* Wk =(const float*)d_in[9];
  const float* gk =(const float*)d_in[10];
  const float* bk =(const float*)d_in[11];
  const float* fc1w=(const float*)d_in[12];
  const float* fc1b=(const float*)d_in[13];
  const float* fc2w=(const float*)d_in[14];
  const float* fc2b=(const float*)d_in[15];
  const float* ksw =(const float*)d_in[16];
  float* out=(float*)d_out;

  float *pConv,*pk0,*pk1,*pk2;
  __nv_bfloat162 *pHiA,*pLoA,*pHiB,*pLoB;
  uint32_t* pW;
  cudaGetSymbolAddress((void**)&pConv, g_conv);
  cudaGetSymbolAddress((void**)&pk0, g_kx0);
  cudaGetSymbolAddress((void**)&pk1, g_kx1);
  cudaGetSymbolAddress((void**)&pk2, g_kx2);
  cudaGetSymbolAddress((void**)&pHiA, g_hiA);
  cudaGetSymbolAddress((void**)&pLoA, g_loA);
  cudaGetSymbolAddress((void**)&pHiB, g_hiB);
  cudaGetSymbolAddress((void**)&pLoB, g_loB);
  cudaGetSymbolAddress((void**)&pW,  g_wswz);

  cudaFuncSetAttribute(conv_mma, cudaFuncAttributeMaxDynamicSharedMemorySize, SM_DYN);

  wprep_kernel<<<(5*KN*4096 + 255)/256, 256>>>(W1, W2, Wk);
  cvt_kernel<<<NPTS*CH/4/256, 256>>>((const float4*)feats, pHiA, pLoA);

  struct Step {
    const __nv_bfloat16 *hi, *lo; const uint32_t* bw;
    const float *g, *b; int relu;
    float* fout; __nv_bfloat162 *ho, *loo;
  };
  Step steps[5] = {
    {(const __nv_bfloat16*)pHiA,(const __nv_bfloat16*)pLoA, pW + 0*KN*4096, g1,      b1,      1, nullptr, pHiB, pLoB},
    {(const __nv_bfloat16*)pHiB,(const __nv_bfloat16*)pLoB, pW + 1*KN*4096, g2,      b2,      0, nullptr, pHiA, pLoA},
    {(const __nv_bfloat16*)pHiA,(const __nv_bfloat16*)pLoA, pW + 2*KN*4096, gk,      bk,      1, pk0,     pHiB, pLoB},
    {(const __nv_bfloat16*)pHiB,(const __nv_bfloat16*)pLoB, pW + 3*KN*4096, gk+CH,   bk+CH,   1, pk1,     pHiA, pLoA},
    {(const __nv_bfloat16*)pHiA,(const __nv_bfloat16*)pLoA, pW + 4*KN*4096, gk+2*CH, bk+2*CH, 1, pk2,     nullptr, nullptr},
  };
  for (int s=0;s<5;s++){
    clear_stats_kernel<<<1,64>>>();
    conv_mma<<<NPTS/128, 256, SM_DYN>>>(steps[s].hi, steps[s].lo, nbr, steps[s].bw, pConv);
    bn2_kernel<<<NPTS*CH/4/256, 256>>>(pConv, steps[s].g, steps[s].b, steps[s].relu,
                                       steps[s].fout, steps[s].ho, steps[s].loo);
  }
  clear_seg_kernel<<<1, NB*CAQ>>>();
  seg_kernel<<<200, CAQ>>>(bidx);
  fc_kernel<<<1,256>>>(bidx, fc1w, fc1b, fc2w, fc2b, ksw);
  final_kernel<<<(NPTS*CH)/256, 256>>>(feats, bidx, out);
}

// round 8
// speedup vs baseline: 2.9342x; 1.1283x over previous
#include <cuda_runtime.h>
#include <cuda_fp16.h>
#include <math.h>
#include <float.h>
#include <stdint.h>

#define NPTS 80000
#define CH   64
#define KN   27
#define NB   2
#define NXX  3
#define CAQ  192
#define HID  12

// ---------------- scratch (device globals; no allocation allowed) ----------
__device__ float g_conv[NPTS*CH];
__device__ float g_kx0[NPTS*CH];
__device__ float g_kx1[NPTS*CH];
__device__ float g_kx2[NPTS*CH];
__device__ __half2 g_hiA[NPTS*CH/2];
__device__ __half2 g_loA[NPTS*CH/2];
__device__ __half2 g_hiB[NPTS*CH/2];
__device__ __half2 g_loB[NPTS*CH/2];
__device__ uint32_t g_wswz[5*KN*2048];      // W_hi fp16, mma-fragment packed (8KB/tap)
__device__ float g_sum[CH], g_sumsq[CH];
__device__ float g_segsum[NB*CAQ], g_segmax[NB*CAQ], g_att[NB*CAQ], g_wsig[NXX];

// ---------------- helpers ----------------------------------------------------
__device__ __forceinline__ uint32_t smem_u32(const void* p){
  uint32_t a;
  asm("{ .reg .u64 t; cvta.to.shared.u64 t, %1; cvt.u32.u64 %0, t; }" : "=r"(a) : "l"(p));
  return a;
}
__device__ __forceinline__ void ldsm_x4(uint32_t addr, uint32_t* r){
  asm volatile("ldmatrix.sync.aligned.m8n8.x4.shared.b16 {%0,%1,%2,%3}, [%4];"
    : "=r"(r[0]),"=r"(r[1]),"=r"(r[2]),"=r"(r[3]) : "r"(addr));
}
__device__ __forceinline__ void hmma(float* c, const uint32_t* a, uint32_t b0, uint32_t b1){
  asm volatile(
    "mma.sync.aligned.m16n8k16.row.col.f32.f16.f16.f32 "
    "{%0,%1,%2,%3}, {%4,%5,%6,%7}, {%8,%9}, {%0,%1,%2,%3};"
    : "+f"(c[0]), "+f"(c[1]), "+f"(c[2]), "+f"(c[3])
    : "r"(a[0]), "r"(a[1]), "r"(a[2]), "r"(a[3]), "r"(b0), "r"(b1));
}
__device__ __forceinline__ void cp16z(uint32_t sdst, const void* gsrc, int srcsz){
  asm volatile("cp.async.cg.shared.global [%0], [%1], 16, %2;" :: "r"(sdst), "l"(gsrc), "r"(srcsz));
}
#define CP_COMMIT() asm volatile("cp.async.commit_group;" ::: "memory")
#define CP_WAIT1()  asm volatile("cp.async.wait_group 1;" ::: "memory")
#define PAIR_BAR(id) asm volatile("bar.sync %0, 64;" :: "r"(id) : "memory")

__device__ __forceinline__ void atomicMaxFloat(float* addr, float val){
  int* ai = (int*)addr;
  int old = *ai;
  while (true){
    float fo = __int_as_float(old);
    if (fo >= val) break;
    int assumed = old;
    old = atomicCAS(ai, assumed, __float_as_int(val));
    if (old == assumed) break;
  }
}

// ---------------- weight prep: pack W_hi into mma B-fragment order ----------
// Per tap: u32 slot = ((wn*4+q)*2+quad)*128 + L*4 + r
//   n  = wn*32 + quad*16 + (r>>1)*8 + (L>>2)
//   kk = q*16 + (L&3)*2 + (r&1)*8
__global__ void wprep_kernel(const float* __restrict__ W1,
                             const float* __restrict__ W2,
                             const float* __restrict__ Wk){
  int gid = blockIdx.x*256 + threadIdx.x;
  if (gid >= 5*KN*2048) return;
  int slot = gid & 2047;
  int tk = gid >> 11;
  int l = tk/KN, k = tk - l*KN;
  const float* Ws = (l==0)? W1 : (l==1)? W2 : (Wk + (size_t)(l-2)*KN*CH*CH);
  int r    = slot & 3;
  int L    = (slot >> 2) & 31;
  int rest = slot >> 7;
  int quad = rest & 1;
  int q    = (rest >> 1) & 3;
  int wn   = rest >> 3;
  int n  = wn*32 + quad*16 + (r>>1)*8 + (L>>2);
  int kk = q*16 + (L&3)*2 + (r&1)*8;
  __half b0 = __float2half(Ws[k*CH*CH + kk*CH + n]);
  __half b1 = __float2half(Ws[k*CH*CH + (kk+1)*CH + n]);
  g_wswz[tk*2048 + slot] =
      (uint32_t)__half_as_ushort(b0) | ((uint32_t)__half_as_ushort(b1) << 16);
}

// ---------------- fp32 -> (hi,lo) fp16 split of layer-0 input ---------------
__global__ void cvt_kernel(const float4* __restrict__ x,
                           __half2* __restrict__ ho,
                           __half2* __restrict__ lo){
  int i4 = blockIdx.x*256 + threadIdx.x;
  float4 v = x[i4];
  __half h0=__float2half(v.x), h1=__float2half(v.y),
         h2=__float2half(v.z), h3=__float2half(v.w);
  ho[2*i4]   = __halves2half2(h0,h1);
  ho[2*i4+1] = __halves2half2(h2,h3);
  lo[2*i4]   = __halves2half2(__float2half(v.x-__half2float(h0)),
                              __float2half(v.y-__half2float(h1)));
  lo[2*i4+1] = __halves2half2(__float2half(v.z-__half2float(h2)),
                              __float2half(v.w-__half2float(h3)));
}

// ---------------- HMMA gathered conv -----------------------------------------
// A: smem 128 rows x 256B ([hi|lo] fp16), TRIPLE-buffered (96KB), 1 pair-bar/tap.
// B: registers via LDG.128 from fragment-packed gmem (L2-hot), per-q double buffer.
// nbr: prefetched into smem once per block.
// 2-pass fp16 compensation: (A_hi + A_lo) x W_hi.
#define NBR_OFF 98304
#define SM_DYN (98304 + 13824 + 1024)

__device__ __forceinline__ void ldgB(const uint4* __restrict__ bw,
                                     int k, int q, int wn, int L, uint32_t* B){
  const uint4* p = bw + (size_t)k*512 + (size_t)((wn*4 + q)*2)*32 + L;
  uint4 v0 = __ldg(p);
  uint4 v1 = __ldg(p + 32);
  B[0]=v0.x; B[1]=v0.y; B[2]=v0.z; B[3]=v0.w;
  B[4]=v1.x; B[5]=v1.y; B[6]=v1.z; B[7]=v1.w;
}

__device__ __forceinline__ void fillA(
    int k, int buf, int t, uint32_t sb, const int* __restrict__ snbr,
    const __half* __restrict__ hi, const __half* __restrict__ lo)
{
  int r = (t>>6)*32 + ((t&63)>>1);   // pair-local rows
  int half = t & 1;
  int idx = snbr[r*KN + k];
  int sz = idx>=0 ? 16 : 0;
  int sidx = idx>=0 ? idx : 0;
  const char* asrc = (const char*)((half? lo: hi) + (size_t)sidx*CH);
  uint32_t abase = sb + buf*32768 + (uint32_t)r*256;
  int xr = r & 7;
#pragma unroll
  for (int j=0;j<8;j++){
    int c = half*8 + j;
    int sw = c ^ xr;
    cp16z(abase + sw*16, asrc + j*16, sz);
  }
}

__global__ void __launch_bounds__(256,2) conv_mma(
    const __half* __restrict__ hi, const __half* __restrict__ lo,
    const int* __restrict__ nbr, const uint32_t* __restrict__ bswz,
    float* __restrict__ dst)
{
  extern __shared__ char smraw[];
  char* sm = (char*)(((uintptr_t)smraw + 1023) & ~(uintptr_t)1023);
  const uint32_t sb = smem_u32(sm);
  int* snbr = (int*)(sm + NBR_OFF);
  __shared__ float sred[128];
  const uint4* bw = (const uint4*)bswz;

  const int t   = threadIdx.x;
  const int L   = t & 31;
  const int wid = t >> 5;
  const int wm  = wid >> 1;
  const int wn  = wid & 1;
  const int row0 = blockIdx.x * 128;
  const int barid = 1 + wm;

  if (t < 128) sred[t] = 0.f;

  // prefetch neighbor indices (contiguous slice)
  {
    const int* src = nbr + (size_t)row0*KN;
#pragma unroll
    for (int i = 0; i < 14; i++){
      int o = t + i*256;
      if (o < 128*KN) snbr[o] = src[o];
    }
  }
  __syncthreads();

  float acc[2][4][4];
#pragma unroll
  for (int s=0;s<2;s++)
#pragma unroll
    for (int nb=0;nb<4;nb++)
#pragma unroll
      for (int i=0;i<4;i++) acc[s][nb][i]=0.f;

  // lane-constant ldmatrix address pieces (A only)
  const int arow_l  = ((L>>3)&1)*8 + (L&7);
  const int a_clane = (L>>4);
  const int arow    = wm*32 + arow_l;
  const int axor    = arow & 7;

  fillA(0, 0, t, sb, snbr, hi, lo); CP_COMMIT();
  fillA(1, 1, t, sb, snbr, hi, lo); CP_COMMIT();

  uint32_t Bb0[8], Bb1[8];
  ldgB(bw, 0, 0, wn, L, Bb0);

  int buf  = 0;   // buffer for tap k
  int bufN = 2;   // buffer to fill with tap k+2

  for (int k = 0; k < KN; k++){
    CP_WAIT1();
    PAIR_BAR(barid);

    // fill tap k+2 (writes buffer consumed at tap k-1; A is pair-private)
    if (k+2 < KN) fillA(k+2, bufN, t, sb, snbr, hi, lo);
    CP_COMMIT();

    const uint32_t Arow = sb + (uint32_t)buf*32768 + (uint32_t)arow*256;

#pragma unroll
    for (int q=0; q<4; q++){
      uint32_t* Bcur = (q&1) ? Bb1 : Bb0;
      uint32_t* Bnxt = (q&1) ? Bb0 : Bb1;
      if (q < 3) ldgB(bw, k, q+1, wn, L, Bnxt);
      else       ldgB(bw, (k+1<KN)?(k+1):k, 0, wn, L, Bnxt);

      const int c_hi = q*2;
      const int c_lo = c_hi + 8;

      uint32_t Ah0[4], Ah1[4], T0[4], T1[4];
      uint32_t ah = Arow + (uint32_t)(((c_hi + a_clane) ^ axor)*16);
      ldsm_x4(ah, Ah0);
      ldsm_x4(ah + 16*256, Ah1);
      uint32_t al = Arow + (uint32_t)(((c_lo + a_clane) ^ axor)*16);
      ldsm_x4(al, T0);
      ldsm_x4(al + 16*256, T1);

      // pass 0: A_hi x W_hi
      hmma(acc[0][0], Ah0, Bcur[0], Bcur[1]);
      hmma(acc[0][1], Ah0, Bcur[2], Bcur[3]);
      hmma(acc[0][2], Ah0, Bcur[4], Bcur[5]);
      hmma(acc[0][3], Ah0, Bcur[6], Bcur[7]);
      hmma(acc[1][0], Ah1, Bcur[0], Bcur[1]);
      hmma(acc[1][1], Ah1, Bcur[2], Bcur[3]);
      hmma(acc[1][2], Ah1, Bcur[4], Bcur[5]);
      hmma(acc[1][3], Ah1, Bcur[6], Bcur[7]);
      // pass 1: A_lo x W_hi
      hmma(acc[0][0], T0,  Bcur[0], Bcur[1]);
      hmma(acc[0][1], T0,  Bcur[2], Bcur[3]);
      hmma(acc[0][2], T0,  Bcur[4], Bcur[5]);
      hmma(acc[0][3], T0,  Bcur[6], Bcur[7]);
      hmma(acc[1][0], T1,  Bcur[0], Bcur[1]);
      hmma(acc[1][1], T1,  Bcur[2], Bcur[3]);
      hmma(acc[1][2], T1,  Bcur[4], Bcur[5]);
      hmma(acc[1][3], T1,  Bcur[6], Bcur[7]);
    }
    buf  = (buf  == 2) ? 0 : buf+1;
    bufN = (bufN == 2) ? 0 : bufN+1;
  }

  // ---- epilogue: stores + fused per-channel stats
#pragma unroll
  for (int s=0;s<2;s++){
    int r = row0 + wm*32 + s*16 + (L>>2);
#pragma unroll
    for (int nb=0;nb<4;nb++){
      int col = wn*32 + nb*8 + (L&3)*2;
      float* c = acc[s][nb];
      *(float2*)&dst[(size_t)r*CH + col]     = make_float2(c[0], c[1]);
      *(float2*)&dst[(size_t)(r+8)*CH + col] = make_float2(c[2], c[3]);
    }
  }
#pragma unroll
  for (int nb=0;nb<4;nb++){
    float sc0=0.f, sc1=0.f, qc0=0.f, qc1=0.f;
#pragma unroll
    for (int s=0;s<2;s++){
      float* c = acc[s][nb];
      sc0 += c[0]+c[2]; qc0 += c[0]*c[0]+c[2]*c[2];
      sc1 += c[1]+c[3]; qc1 += c[1]*c[1]+c[3]*c[3];
    }
#pragma unroll
    for (int m=4;m<32;m<<=1){
      sc0 += __shfl_xor_sync(0xFFFFFFFFu, sc0, m);
      sc1 += __shfl_xor_sync(0xFFFFFFFFu, sc1, m);
      qc0 += __shfl_xor_sync(0xFFFFFFFFu, qc0, m);
      qc1 += __shfl_xor_sync(0xFFFFFFFFu, qc1, m);
    }
    if (L < 4){
      int col = wn*32 + nb*8 + L*2;
      atomicAdd(&sred[col],    sc0); atomicAdd(&sred[col+1],    sc1);
      atomicAdd(&sred[64+col], qc0); atomicAdd(&sred[64+col+1], qc1);
    }
  }
  __syncthreads();
  if (t < 64){
    atomicAdd(&g_sum[t],   sred[t]);
    atomicAdd(&g_sumsq[t], sred[64+t]);
  }
}

// ---------------- stats clear ----------------------------------------------
__global__ void clear_stats_kernel(){
  int t = threadIdx.x; if (t < CH){ g_sum[t]=0.f; g_sumsq[t]=0.f; }
}

// ---------------- BN apply + emit fp32 and/or fp16 hi/lo --------------------
__global__ void bn2_kernel(const float* __restrict__ x, const float* __restrict__ gg,
                           const float* __restrict__ bb, int relu,
                           float* __restrict__ fout,
                           __half2* __restrict__ ho,
                           __half2* __restrict__ lo){
  __shared__ float sc[64], bi[64];
  int t = threadIdx.x;
  if (t < 64){
    float m = g_sum[t]*(1.f/NPTS);
    float v = g_sumsq[t]*(1.f/NPTS) - m*m;
    float s = rsqrtf(v + 1e-5f) * gg[t];
    sc[t] = s; bi[t] = bb[t] - m*s;
  }
  __syncthreads();
  int i4 = blockIdx.x*256 + t;
  float4 v = ((const float4*)x)[i4];
  int c = (i4 & 15)*4;
  v.x = v.x*sc[c]+bi[c];     v.y = v.y*sc[c+1]+bi[c+1];
  v.z = v.z*sc[c+2]+bi[c+2]; v.w = v.w*sc[c+3]+bi[c+3];
  if (relu){ v.x=fmaxf(v.x,0.f); v.y=fmaxf(v.y,0.f); v.z=fmaxf(v.z,0.f); v.w=fmaxf(v.w,0.f); }
  if (fout) ((float4*)fout)[i4] = v;
  if (ho){
    __half h0=__float2half(v.x), h1=__float2half(v.y),
           h2=__float2half(v.z), h3=__float2half(v.w);
    ho[2*i4]   = __halves2half2(h0,h1);
    ho[2*i4+1] = __halves2half2(h2,h3);
    lo[2*i4]   = __halves2half2(__float2half(v.x-__half2float(h0)),
                                __float2half(v.y-__half2float(h1)));
    lo[2*i4+1] = __halves2half2(__float2half(v.z-__half2float(h2)),
                                __float2half(v.w-__half2float(h3)));
  }
}

// ---------------- segment sum/max over batches (B=2), 192 channels ---------
__global__ void clear_seg_kernel(){
  int t = threadIdx.x; if (t < NB*CAQ){ g_segsum[t]=0.f; g_segmax[t]=-FLT_MAX; }
}
__global__ void seg_kernel(const int* __restrict__ bidx){
  int j = threadIdx.x;
  const float* kxp = (j<64)? g_kx0 : ((j<128)? g_kx1 : g_kx2);
  int c = j & 63;
  int n0 = blockIdx.x*400, n1 = n0+400;
  float s0=0.f, s1=0.f, m0=-FLT_MAX, m1=-FLT_MAX;
  for (int n=n0;n<n1;n++){
    float v = kxp[n*CH + c];
    if (bidx[n]==0){ s0+=v; m0=fmaxf(m0,v); } else { s1+=v; m1=fmaxf(m1,v); }
  }
  atomicAdd(&g_segsum[j], s0);
  atomicAdd(&g_segsum[CAQ+j], s1);
  atomicMaxFloat(&g_segmax[j], m0);
  atomicMaxFloat(&g_segmax[CAQ+j], m1);
}

// ---------------- tiny FC + sigmoid attention ------------------------------
__global__ void fc_kernel(const int* __restrict__ bidx,
    const float* __restrict__ w1, const float* __restrict__ b1,
    const float* __restrict__ w2, const float* __restrict__ b2,
    const float* __restrict__ ksw)
{
  __shared__ float ha[NB][HID], hm[NB][HID];
  __shared__ int red[256];
  __shared__ int scnt[NB];
  int t = threadIdx.x;
  int c0 = 0;
  for (int n=t; n<NPTS; n+=256) c0 += (bidx[n]==0);
  red[t]=c0; __syncthreads();
  for (int s=128;s>0;s>>=1){ if (t<s) red[t]+=red[t+s]; __syncthreads(); }
  if (t==0){ scnt[0]=red[0]; scnt[1]=NPTS-red[0]; }
  __syncthreads();
  if (t<48){
    int which = t/24;
    int b  = (t/12)%2;
    int tt = t%12;
    float s = b1[tt];
    float inv = 1.f/(float)scnt[b];
    for (int j=0;j<CAQ;j++){
      float z = which ? g_segmax[b*CAQ+j] : g_segsum[b*CAQ+j]*inv;
      s += z * w1[j*HID+tt];
    }
    s = fmaxf(s,0.f);
    if (which) hm[b][tt]=s; else ha[b][tt]=s;
  }
  __syncthreads();
  for (int o=t; o<NB*CAQ; o+=256){
    int b=o/CAQ, j=o%CAQ;
    float sa=b2[j], sm=b2[j];
    for (int tt=0;tt<HID;tt++){ sa += ha[b][tt]*w2[tt*CAQ+j]; sm += hm[b][tt]*w2[tt*CAQ+j]; }
    float s = sa+sm;
    g_att[o] = 1.f/(1.f+expf(-s));
  }
  if (t<NXX) g_wsig[t] = 1.f/(1.f+expf(-ksw[t]));
}

// ---------------- fusion epilogue ------------------------------------------
__device__ __forceinline__ float kx_read(int sel, int off){
  return sel==0 ? g_kx0[off] : (sel==1 ? g_kx1[off] : g_kx2[off]);
}
__global__ void final_kernel(const float* __restrict__ feats,
                             const int* __restrict__ bidx,
                             float* __restrict__ out){
  int i = blockIdx.x*256 + threadIdx.x;
  int n = i >> 6, c = i & 63;
  int b = bidx[n];
  float acc = feats[i];
#pragma unroll
  for (int ii=0; ii<NXX; ii++){
    int j = 3*c + ii;
    int sel = j >> 6, col = j & 63;
    float xj  = kx_read(sel, n*CH + col);
    float kxi = kx_read(ii, i);
    acc += g_wsig[ii] * (kxi + xj * g_att[b*CAQ + j]);
  }
  out[i] = fmaxf(acc, 0.f);
}

// ---------------- launch ----------------------------------------------------
extern "C" void kernel_launch(void* const* d_in, const int* in_sizes, int n_in,
                              void* d_out, int out_size){
  (void)in_sizes; (void)n_in; (void)out_size;
  const float* feats=(const float*)d_in[0];
  const int*   bidx =(const int*)d_in[1];
  const int*   nbr  =(const int*)d_in[2];
  const float* W1 =(const float*)d_in[3];
  const float* g1 =(const float*)d_in[4];
  const float* b1 =(const float*)d_in[5];
  const float* W2 =(const float*)d_in[6];
  const float* g2 =(const float*)d_in[7];
  const float* b2 =(const float*)d_in[8];
  const float* Wk =(const float*)d_in[9];
  const float* gk =(const float*)d_in[10];
  const float* bk =(const float*)d_in[11];
  const float* fc1w=(const float*)d_in[12];
  const float* fc1b=(const float*)d_in[13];
  const float* fc2w=(const float*)d_in[14];
  const float* fc2b=(const float*)d_in[15];
  const float* ksw =(const float*)d_in[16];
  float* out=(float*)d_out;

  float *pConv,*pk0,*pk1,*pk2;
  __half2 *pHiA,*pLoA,*pHiB,*pLoB;
  uint32_t* pW;
  cudaGetSymbolAddress((void**)&pConv, g_conv);
  cudaGetSymbolAddress((void**)&pk0, g_kx0);
  cudaGetSymbolAddress((void**)&pk1, g_kx1);
  cudaGetSymbolAddress((void**)&pk2, g_kx2);
  cudaGetSymbolAddress((void**)&pHiA, g_hiA);
  cudaGetSymbolAddress((void**)&pLoA, g_loA);
  cudaGetSymbolAddress((void**)&pHiB, g_hiB);
  cudaGetSymbolAddress((void**)&pLoB, g_loB);
  cudaGetSymbolAddress((void**)&pW,  g_wswz);

  cudaFuncSetAttribute(conv_mma, cudaFuncAttributeMaxDynamicSharedMemorySize, SM_DYN);

  wprep_kernel<<<(5*KN*2048 + 255)/256, 256>>>(W1, W2, Wk);
  cvt_kernel<<<NPTS*CH/4/256, 256>>>((const float4*)feats, pHiA, pLoA);

  struct Step {
    const __half *hi, *lo; const uint32_t* bw;
    const float *g, *b; int relu;
    float* fout; __half2 *ho, *loo;
  };
  Step steps[5] = {
    {(const __half*)pHiA,(const __half*)pLoA, pW + 0*KN*2048, g1,      b1,      1, nullptr, pHiB, pLoB},
    {(const __half*)pHiB,(const __half*)pLoB, pW + 1*KN*2048, g2,      b2,      0, nullptr, pHiA, pLoA},
    {(const __half*)pHiA,(const __half*)pLoA, pW + 2*KN*2048, gk,      bk,      1, pk0,     pHiB, pLoB},
    {(const __half*)pHiB,(const __half*)pLoB, pW + 3*KN*2048, gk+CH,   bk+CH,   1, pk1,     pHiA, pLoA},
    {(const __half*)pHiA,(const __half*)pLoA, pW + 4*KN*2048, gk+2*CH, bk+2*CH, 1, pk2,     nullptr, nullptr},
  };
  for (int s=0;s<5;s++){
    clear_stats_kernel<<<1,64>>>();
    conv_mma<<<NPTS/128, 256, SM_DYN>>>(steps[s].hi, steps[s].lo, nbr, steps[s].bw, pConv);
    bn2_kernel<<<NPTS*CH/4/256, 256>>>(pConv, steps[s].g, steps[s].b, steps[s].relu,
                                       steps[s].fout, steps[s].ho, steps[s].loo);
  }
  clear_seg_kernel<<<1, NB*CAQ>>>();
  seg_kernel<<<200, CAQ>>>(bidx);
  fc_kernel<<<1,256>>>(bidx, fc1w, fc1b, fc2w, fc2b, ksw);
  final_kernel<<<(NPTS*CH)/256, 256>>>(feats, bidx, out);
}

// round 9
// speedup vs baseline: 2.9700x; 1.0122x over previous
#include <cuda_runtime.h>
#include <cuda_fp16.h>
#include <math.h>
#include <float.h>
#include <stdint.h>

#define NPTS 80000
#define CH   64
#define KN   27
#define NB   2
#define NXX  3
#define CAQ  192
#define HID  12

// ---------------- scratch (device globals; no allocation allowed) ----------
__device__ float g_conv[NPTS*CH];
__device__ float g_kx0[NPTS*CH];
__device__ float g_kx1[NPTS*CH];
__device__ float g_kx2[NPTS*CH];
__device__ __half2 g_hiA[NPTS*CH/2];
__device__ __half2 g_loA[NPTS*CH/2];
__device__ __half2 g_hiB[NPTS*CH/2];
__device__ __half2 g_loB[NPTS*CH/2];
__device__ uint32_t g_wswz[5*KN*2048];      // W_hi fp16, mma-fragment packed (8KB/tap)
__device__ float g_sum[CH], g_sumsq[CH];
__device__ float g_segsum[NB*CAQ], g_segmax[NB*CAQ], g_att[NB*CAQ], g_wsig[NXX];

// ---------------- helpers ----------------------------------------------------
__device__ __forceinline__ uint32_t smem_u32(const void* p){
  uint32_t a;
  asm("{ .reg .u64 t; cvta.to.shared.u64 t, %1; cvt.u32.u64 %0, t; }" : "=r"(a) : "l"(p));
  return a;
}
__device__ __forceinline__ void ldsm_x4(uint32_t addr, uint32_t* r){
  asm volatile("ldmatrix.sync.aligned.m8n8.x4.shared.b16 {%0,%1,%2,%3}, [%4];"
    : "=r"(r[0]),"=r"(r[1]),"=r"(r[2]),"=r"(r[3]) : "r"(addr));
}
__device__ __forceinline__ void hmma(float* c, const uint32_t* a, uint32_t b0, uint32_t b1){
  asm volatile(
    "mma.sync.aligned.m16n8k16.row.col.f32.f16.f16.f32 "
    "{%0,%1,%2,%3}, {%4,%5,%6,%7}, {%8,%9}, {%0,%1,%2,%3};"
    : "+f"(c[0]), "+f"(c[1]), "+f"(c[2]), "+f"(c[3])
    : "r"(a[0]), "r"(a[1]), "r"(a[2]), "r"(a[3]), "r"(b0), "r"(b1));
}
__device__ __forceinline__ void cp16z(uint32_t sdst, const void* gsrc, int srcsz){
  asm volatile("cp.async.cg.shared.global [%0], [%1], 16, %2;" :: "r"(sdst), "l"(gsrc), "r"(srcsz));
}
#define CP_COMMIT() asm volatile("cp.async.commit_group;" ::: "memory")
#define CP_WAIT1()  asm volatile("cp.async.wait_group 1;" ::: "memory")

__device__ __forceinline__ void atomicMaxFloat(float* addr, float val){
  int* ai = (int*)addr;
  int old = *ai;
  while (true){
    float fo = __int_as_float(old);
    if (fo >= val) break;
    int assumed = old;
    old = atomicCAS(ai, assumed, __float_as_int(val));
    if (old == assumed) break;
  }
}

// ---------------- weight prep: pack W_hi into mma B-fragment order ----------
// Per tap: u32 slot = ((wn*4+q)*2+quad)*128 + L*4 + r
//   n  = wn*32 + quad*16 + (r>>1)*8 + (L>>2)
//   kk = q*16 + (L&3)*2 + (r&1)*8
__global__ void wprep_kernel(const float* __restrict__ W1,
                             const float* __restrict__ W2,
                             const float* __restrict__ Wk){
  int gid = blockIdx.x*256 + threadIdx.x;
  if (gid >= 5*KN*2048) return;
  int slot = gid & 2047;
  int tk = gid >> 11;
  int l = tk/KN, k = tk - l*KN;
  const float* Ws = (l==0)? W1 : (l==1)? W2 : (Wk + (size_t)(l-2)*KN*CH*CH);
  int r    = slot & 3;
  int L    = (slot >> 2) & 31;
  int rest = slot >> 7;
  int quad = rest & 1;
  int q    = (rest >> 1) & 3;
  int wn   = rest >> 3;
  int n  = wn*32 + quad*16 + (r>>1)*8 + (L>>2);
  int kk = q*16 + (L&3)*2 + (r&1)*8;
  __half b0 = __float2half(Ws[k*CH*CH + kk*CH + n]);
  __half b1 = __float2half(Ws[k*CH*CH + (kk+1)*CH + n]);
  g_wswz[tk*2048 + slot] =
      (uint32_t)__half_as_ushort(b0) | ((uint32_t)__half_as_ushort(b1) << 16);
}

// ---------------- fp32 -> (hi,lo) fp16 split of layer-0 input ---------------
__global__ void cvt_kernel(const float4* __restrict__ x,
                           __half2* __restrict__ ho,
                           __half2* __restrict__ lo){
  int i4 = blockIdx.x*256 + threadIdx.x;
  float4 v = x[i4];
  __half h0=__float2half(v.x), h1=__float2half(v.y),
         h2=__float2half(v.z), h3=__float2half(v.w);
  ho[2*i4]   = __halves2half2(h0,h1);
  ho[2*i4+1] = __halves2half2(h2,h3);
  lo[2*i4]   = __halves2half2(__float2half(v.x-__half2float(h0)),
                              __float2half(v.y-__half2float(h1)));
  lo[2*i4+1] = __halves2half2(__float2half(v.z-__half2float(h2)),
                              __float2half(v.w-__half2float(h3)));
}

// ---------------- HMMA gathered conv -----------------------------------------
// Warp-private tiling: 8 warps x (M=16 rows, N=64). A: per-warp 4KB x3 ring
// (96KB total), NO mainloop barriers. B: registers via LDG.128 (fragment-packed
// gmem, L2-hot), per-q double buffer. nbr in smem. 2-pass fp16 compensation.
#define NBR_OFF 98304
#define SM_DYN (98304 + 13824 + 1024)

__device__ __forceinline__ void ldgB64(const uint4* __restrict__ bw,
                                       int k, int q, int L, uint32_t* B){
  const uint4* p0 = bw + (size_t)k*512 + (size_t)(q*2)*32 + L;       // n 0..31
  const uint4* p1 = p0 + 8*32;                                       // n 32..63
  uint4 v0 = __ldg(p0);
  uint4 v1 = __ldg(p0 + 32);
  uint4 v2 = __ldg(p1);
  uint4 v3 = __ldg(p1 + 32);
  B[0]=v0.x;  B[1]=v0.y;  B[2]=v0.z;  B[3]=v0.w;
  B[4]=v1.x;  B[5]=v1.y;  B[6]=v1.z;  B[7]=v1.w;
  B[8]=v2.x;  B[9]=v2.y;  B[10]=v2.z; B[11]=v2.w;
  B[12]=v3.x; B[13]=v3.y; B[14]=v3.z; B[15]=v3.w;
}

// warp-private A fill: 16 rows x 256B ([hi|lo]); lane L -> row L>>1, half L&1
__device__ __forceinline__ void fillA(
    int k, uint32_t abase, int w, int L, const int* __restrict__ snbr,
    const __half* __restrict__ hi, const __half* __restrict__ lo)
{
  int rl   = L >> 1;
  int half = L & 1;
  int idx = snbr[(w*16 + rl)*KN + k];
  int sz = idx>=0 ? 16 : 0;
  int sidx = idx>=0 ? idx : 0;
  const char* asrc = (const char*)((half? lo: hi) + (size_t)sidx*CH);
  uint32_t rbase = abase + (uint32_t)rl*256;
  int xr = rl & 7;
#pragma unroll
  for (int j=0;j<8;j++){
    int c = half*8 + j;
    int sw = c ^ xr;
    cp16z(rbase + sw*16, asrc + j*16, sz);
  }
}

__global__ void __launch_bounds__(256,2) conv_mma(
    const __half* __restrict__ hi, const __half* __restrict__ lo,
    const int* __restrict__ nbr, const uint32_t* __restrict__ bswz,
    float* __restrict__ dst)
{
  extern __shared__ char smraw[];
  char* sm = (char*)(((uintptr_t)smraw + 1023) & ~(uintptr_t)1023);
  const uint32_t sb = smem_u32(sm);
  int* snbr = (int*)(sm + NBR_OFF);
  __shared__ float sred[128];
  const uint4* bw = (const uint4*)bswz;

  const int t   = threadIdx.x;
  const int L   = t & 31;
  const int w   = t >> 5;           // warp id 0..7, owns rows 16w..16w+15
  const int row0 = blockIdx.x * 128;

  if (t < 128) sred[t] = 0.f;

  // prefetch neighbor indices (contiguous slice)
  {
    const int* src = nbr + (size_t)row0*KN;
#pragma unroll
    for (int i = 0; i < 14; i++){
      int o = t + i*256;
      if (o < 128*KN) snbr[o] = src[o];
    }
  }
  __syncthreads();

  float acc[8][4];
#pragma unroll
  for (int nb=0;nb<8;nb++)
#pragma unroll
    for (int i=0;i<4;i++) acc[nb][i]=0.f;

  // lane-constant ldmatrix address pieces
  const int arow_l  = ((L>>3)&1)*8 + (L&7);   // 0..15
  const int a_clane = (L>>4);
  const int axor    = arow_l & 7;
  const uint32_t wbase = sb + (uint32_t)w*12288;   // warp's 3-buffer ring

  fillA(0, wbase,        w, L, snbr, hi, lo); CP_COMMIT();
  fillA(1, wbase + 4096, w, L, snbr, hi, lo); CP_COMMIT();

  uint32_t Bb0[16], Bb1[16];
  ldgB64(bw, 0, 0, L, Bb0);

  int buf  = 0;
  int bufN = 2;

  for (int k = 0; k < KN; k++){
    CP_WAIT1();

    // warp-private: fill tap k+2 into the ring slot consumed at tap k-1
    if (k+2 < KN) fillA(k+2, wbase + (uint32_t)bufN*4096, w, L, snbr, hi, lo);
    CP_COMMIT();

    const uint32_t Arow = wbase + (uint32_t)buf*4096 + (uint32_t)arow_l*256;

#pragma unroll
    for (int q=0; q<4; q++){
      uint32_t* Bcur = (q&1) ? Bb1 : Bb0;
      uint32_t* Bnxt = (q&1) ? Bb0 : Bb1;
      if (q < 3) ldgB64(bw, k, q+1, L, Bnxt);
      else       ldgB64(bw, (k+1<KN)?(k+1):k, 0, L, Bnxt);

      const int c_hi = q*2;
      const int c_lo = c_hi + 8;

      uint32_t Ah[4], Al[4];
      ldsm_x4(Arow + (uint32_t)(((c_hi + a_clane) ^ axor)*16), Ah);
      ldsm_x4(Arow + (uint32_t)(((c_lo + a_clane) ^ axor)*16), Al);

#pragma unroll
      for (int nb=0; nb<8; nb++){
        hmma(acc[nb], Ah, Bcur[2*nb], Bcur[2*nb+1]);
        hmma(acc[nb], Al, Bcur[2*nb], Bcur[2*nb+1]);
      }
    }
    buf  = (buf  == 2) ? 0 : buf+1;
    bufN = (bufN == 2) ? 0 : bufN+1;
  }

  // ---- epilogue: stores + fused per-channel stats
  {
    int r0 = row0 + w*16 + (L>>2);
#pragma unroll
    for (int nb=0;nb<8;nb++){
      int col = nb*8 + (L&3)*2;
      float* c = acc[nb];
      *(float2*)&dst[(size_t)r0*CH + col]     = make_float2(c[0], c[1]);
      *(float2*)&dst[(size_t)(r0+8)*CH + col] = make_float2(c[2], c[3]);
    }
  }
#pragma unroll
  for (int nb=0;nb<8;nb++){
    float* c = acc[nb];
    float sc0 = c[0]+c[2], sc1 = c[1]+c[3];
    float qc0 = c[0]*c[0]+c[2]*c[2], qc1 = c[1]*c[1]+c[3]*c[3];
#pragma unroll
    for (int m=4;m<32;m<<=1){
      sc0 += __shfl_xor_sync(0xFFFFFFFFu, sc0, m);
      sc1 += __shfl_xor_sync(0xFFFFFFFFu, sc1, m);
      qc0 += __shfl_xor_sync(0xFFFFFFFFu, qc0, m);
      qc1 += __shfl_xor_sync(0xFFFFFFFFu, qc1, m);
    }
    if (L < 4){
      int col = nb*8 + L*2;
      atomicAdd(&sred[col],    sc0); atomicAdd(&sred[col+1],    sc1);
      atomicAdd(&sred[64+col], qc0); atomicAdd(&sred[64+col+1], qc1);
    }
  }
  __syncthreads();
  if (t < 64){
    atomicAdd(&g_sum[t],   sred[t]);
    atomicAdd(&g_sumsq[t], sred[64+t]);
  }
}

// ---------------- stats clear ----------------------------------------------
__global__ void clear_stats_kernel(){
  int t = threadIdx.x; if (t < CH){ g_sum[t]=0.f; g_sumsq[t]=0.f; }
}

// ---------------- BN apply + emit fp32 and/or fp16 hi/lo --------------------
__global__ void bn2_kernel(const float* __restrict__ x, const float* __restrict__ gg,
                           const float* __restrict__ bb, int relu,
                           float* __restrict__ fout,
                           __half2* __restrict__ ho,
                           __half2* __restrict__ lo){
  __shared__ float sc[64], bi[64];
  int t = threadIdx.x;
  if (t < 64){
    float m = g_sum[t]*(1.f/NPTS);
    float v = g_sumsq[t]*(1.f/NPTS) - m*m;
    float s = rsqrtf(v + 1e-5f) * gg[t];
    sc[t] = s; bi[t] = bb[t] - m*s;
  }
  __syncthreads();
  int i4 = blockIdx.x*256 + t;
  float4 v = ((const float4*)x)[i4];
  int c = (i4 & 15)*4;
  v.x = v.x*sc[c]+bi[c];     v.y = v.y*sc[c+1]+bi[c+1];
  v.z = v.z*sc[c+2]+bi[c+2]; v.w = v.w*sc[c+3]+bi[c+3];
  if (relu){ v.x=fmaxf(v.x,0.f); v.y=fmaxf(v.y,0.f); v.z=fmaxf(v.z,0.f); v.w=fmaxf(v.w,0.f); }
  if (fout) ((float4*)fout)[i4] = v;
  if (ho){
    __half h0=__float2half(v.x), h1=__float2half(v.y),
           h2=__float2half(v.z), h3=__float2half(v.w);
    ho[2*i4]   = __halves2half2(h0,h1);
    ho[2*i4+1] = __halves2half2(h2,h3);
    lo[2*i4]   = __halves2half2(__float2half(v.x-__half2float(h0)),
                                __float2half(v.y-__half2float(h1)));
    lo[2*i4+1] = __halves2half2(__float2half(v.z-__half2float(h2)),
                                __float2half(v.w-__half2float(h3)));
  }
}

// ---------------- segment sum/max over batches (B=2), 192 channels ---------
__global__ void clear_seg_kernel(){
  int t = threadIdx.x; if (t < NB*CAQ){ g_segsum[t]=0.f; g_segmax[t]=-FLT_MAX; }
}
__global__ void seg_kernel(const int* __restrict__ bidx){
  int j = threadIdx.x;
  const float* kxp = (j<64)? g_kx0 : ((j<128)? g_kx1 : g_kx2);
  int c = j & 63;
  int n0 = blockIdx.x*400, n1 = n0+400;
  float s0=0.f, s1=0.f, m0=-FLT_MAX, m1=-FLT_MAX;
  for (int n=n0;n<n1;n++){
    float v = kxp[n*CH + c];
    if (bidx[n]==0){ s0+=v; m0=fmaxf(m0,v); } else { s1+=v; m1=fmaxf(m1,v); }
  }
  atomicAdd(&g_segsum[j], s0);
  atomicAdd(&g_segsum[CAQ+j], s1);
  atomicMaxFloat(&g_segmax[j], m0);
  atomicMaxFloat(&g_segmax[CAQ+j], m1);
}

// ---------------- tiny FC + sigmoid attention ------------------------------
__global__ void fc_kernel(const int* __restrict__ bidx,
    const float* __restrict__ w1, const float* __restrict__ b1,
    const float* __restrict__ w2, const float* __restrict__ b2,
    const float* __restrict__ ksw)
{
  __shared__ float ha[NB][HID], hm[NB][HID];
  __shared__ int red[256];
  __shared__ int scnt[NB];
  int t = threadIdx.x;
  int c0 = 0;
  for (int n=t; n<NPTS; n+=256) c0 += (bidx[n]==0);
  red[t]=c0; __syncthreads();
  for (int s=128;s>0;s>>=1){ if (t<s) red[t]+=red[t+s]; __syncthreads(); }
  if (t==0){ scnt[0]=red[0]; scnt[1]=NPTS-red[0]; }
  __syncthreads();
  if (t<48){
    int which = t/24;
    int b  = (t/12)%2;
    int tt = t%12;
    float s = b1[tt];
    float inv = 1.f/(float)scnt[b];
    for (int j=0;j<CAQ;j++){
      float z = which ? g_segmax[b*CAQ+j] : g_segsum[b*CAQ+j]*inv;
      s += z * w1[j*HID+tt];
    }
    s = fmaxf(s,0.f);
    if (which) hm[b][tt]=s; else ha[b][tt]=s;
  }
  __syncthreads();
  for (int o=t; o<NB*CAQ; o+=256){
    int b=o/CAQ, j=o%CAQ;
    float sa=b2[j], sm=b2[j];
    for (int tt=0;tt<HID;tt++){ sa += ha[b][tt]*w2[tt*CAQ+j]; sm += hm[b][tt]*w2[tt*CAQ+j]; }
    float s = sa+sm;
    g_att[o] = 1.f/(1.f+expf(-s));
  }
  if (t<NXX) g_wsig[t] = 1.f/(1.f+expf(-ksw[t]));
}

// ---------------- fusion epilogue ------------------------------------------
__device__ __forceinline__ float kx_read(int sel, int off){
  return sel==0 ? g_kx0[off] : (sel==1 ? g_kx1[off] : g_kx2[off]);
}
__global__ void final_kernel(const float* __restrict__ feats,
                             const int* __restrict__ bidx,
                             float* __restrict__ out){
  int i = blockIdx.x*256 + threadIdx.x;
  int n = i >> 6, c = i & 63;
  int b = bidx[n];
  float acc = feats[i];
#pragma unroll
  for (int ii=0; ii<NXX; ii++){
    int j = 3*c + ii;
    int sel = j >> 6, col = j & 63;
    float xj  = kx_read(sel, n*CH + col);
    float kxi = kx_read(ii, i);
    acc += g_wsig[ii] * (kxi + xj * g_att[b*CAQ + j]);
  }
  out[i] = fmaxf(acc, 0.f);
}

// ---------------- launch ----------------------------------------------------
extern "C" void kernel_launch(void* const* d_in, const int* in_sizes, int n_in,
                              void* d_out, int out_size){
  (void)in_sizes; (void)n_in; (void)out_size;
  const float* feats=(const float*)d_in[0];
  const int*   bidx =(const int*)d_in[1];
  const int*   nbr  =(const int*)d_in[2];
  const float* W1 =(const float*)d_in[3];
  const float* g1 =(const float*)d_in[4];
  const float* b1 =(const float*)d_in[5];
  const float* W2 =(const float*)d_in[6];
  const float* g2 =(const float*)d_in[7];
  const float* b2 =(const float*)d_in[8];
  const float* Wk =(const float*)d_in[9];
  const float* gk =(const float*)d_in[10];
  const float* bk =(const float*)d_in[11];
  const float* fc1w=(const float*)d_in[12];
  const float* fc1b=(const float*)d_in[13];
  const float* fc2w=(const float*)d_in[14];
  const float* fc2b=(const float*)d_in[15];
  const float* ksw =(const float*)d_in[16];
  float* out=(float*)d_out;

  float *pConv,*pk0,*pk1,*pk2;
  __half2 *pHiA,*pLoA,*pHiB,*pLoB;
  uint32_t* pW;
  cudaGetSymbolAddress((void**)&pConv, g_conv);
  cudaGetSymbolAddress((void**)&pk0, g_kx0);
  cudaGetSymbolAddress((void**)&pk1, g_kx1);
  cudaGetSymbolAddress((void**)&pk2, g_kx2);
  cudaGetSymbolAddress((void**)&pHiA, g_hiA);
  cudaGetSymbolAddress((void**)&pLoA, g_loA);
  cudaGetSymbolAddress((void**)&pHiB, g_hiB);
  cudaGetSymbolAddress((void**)&pLoB, g_loB);
  cudaGetSymbolAddress((void**)&pW,  g_wswz);

  cudaFuncSetAttribute(conv_mma, cudaFuncAttributeMaxDynamicSharedMemorySize, SM_DYN);

  wprep_kernel<<<(5*KN*2048 + 255)/256, 256>>>(W1, W2, Wk);
  cvt_kernel<<<NPTS*CH/4/256, 256>>>((const float4*)feats, pHiA, pLoA);

  struct Step {
    const __half *hi, *lo; const uint32_t* bw;
    const float *g, *b; int relu;
    float* fout; __half2 *ho, *loo;
  };
  Step steps[5] = {
    {(const __half*)pHiA,(const __half*)pLoA, pW + 0*KN*2048, g1,      b1,      1, nullptr, pHiB, pLoB},
    {(const __half*)pHiB,(const __half*)pLoB, pW + 1*KN*2048, g2,      b2,      0, nullptr, pHiA, pLoA},
    {(const __half*)pHiA,(const __half*)pLoA, pW + 2*KN*2048, gk,      bk,      1, pk0,     pHiB, pLoB},
    {(const __half*)pHiB,(const __half*)pLoB, pW + 3*KN*2048, gk+CH,   bk+CH,   1, pk1,     pHiA, pLoA},
    {(const __half*)pHiA,(const __half*)pLoA, pW + 4*KN*2048, gk+2*CH, bk+2*CH, 1, pk2,     nullptr, nullptr},
  };
  for (int s=0;s<5;s++){
    clear_stats_kernel<<<1,64>>>();
    conv_mma<<<NPTS/128, 256, SM_DYN>>>(steps[s].hi, steps[s].lo, nbr, steps[s].bw, pConv);
    bn2_kernel<<<NPTS*CH/4/256, 256>>>(pConv, steps[s].g, steps[s].b, steps[s].relu,
                                       steps[s].fout, steps[s].ho, steps[s].loo);
  }
  clear_seg_kernel<<<1, NB*CAQ>>>();
  seg_kernel<<<200, CAQ>>>(bidx);
  fc_kernel<<<1,256>>>(bidx, fc1w, fc1b, fc2w, fc2b, ksw);
  final_kernel<<<(NPTS*CH)/256, 256>>>(feats, bidx, out);
}

// round 10
// speedup vs baseline: 5.4175x; 1.8241x over previous
#include <cuda_runtime.h>
#include <cuda_fp16.h>
#include <math.h>
#include <float.h>
#include <stdint.h>

#define NPTS 80000
#define CH   64
#define KN   27
#define NB   2
#define NXX  3
#define CAQ  192
#define HID  12

// ---------------- scratch (device globals; no allocation allowed) ----------
__device__ float g_conv[NPTS*CH];
__device__ float g_kx0[NPTS*CH];
__device__ float g_kx1[NPTS*CH];
__device__ float g_kx2[NPTS*CH];
__device__ __half2 g_hiA[NPTS*CH/2];
__device__ __half2 g_hiB[NPTS*CH/2];
__device__ uint32_t g_wswz[5*KN*2048];      // W_hi fp16, mma-fragment packed (8KB/tap)
__device__ float g_sum[CH], g_sumsq[CH];
__device__ float g_segsum[NB*CAQ], g_segmax[NB*CAQ], g_att[NB*CAQ], g_wsig[NXX];

// ---------------- helpers ----------------------------------------------------
__device__ __forceinline__ uint32_t smem_u32(const void* p){
  uint32_t a;
  asm("{ .reg .u64 t; cvta.to.shared.u64 t, %1; cvt.u32.u64 %0, t; }" : "=r"(a) : "l"(p));
  return a;
}
__device__ __forceinline__ void ldsm_x4(uint32_t addr, uint32_t* r){
  asm volatile("ldmatrix.sync.aligned.m8n8.x4.shared.b16 {%0,%1,%2,%3}, [%4];"
    : "=r"(r[0]),"=r"(r[1]),"=r"(r[2]),"=r"(r[3]) : "r"(addr));
}
__device__ __forceinline__ void hmma(float* c, const uint32_t* a, uint32_t b0, uint32_t b1){
  asm volatile(
    "mma.sync.aligned.m16n8k16.row.col.f32.f16.f16.f32 "
    "{%0,%1,%2,%3}, {%4,%5,%6,%7}, {%8,%9}, {%0,%1,%2,%3};"
    : "+f"(c[0]), "+f"(c[1]), "+f"(c[2]), "+f"(c[3])
    : "r"(a[0]), "r"(a[1]), "r"(a[2]), "r"(a[3]), "r"(b0), "r"(b1));
}
__device__ __forceinline__ void cp16z(uint32_t sdst, const void* gsrc, int srcsz){
  asm volatile("cp.async.cg.shared.global [%0], [%1], 16, %2;" :: "r"(sdst), "l"(gsrc), "r"(srcsz));
}
#define CP_COMMIT() asm volatile("cp.async.commit_group;" ::: "memory")
#define CP_WAIT1()  asm volatile("cp.async.wait_group 1;" ::: "memory")
#define PAIR_BAR(id) asm volatile("bar.sync %0, 64;" :: "r"(id) : "memory")

__device__ __forceinline__ void atomicMaxFloat(float* addr, float val){
  int* ai = (int*)addr;
  int old = *ai;
  while (true){
    float fo = __int_as_float(old);
    if (fo >= val) break;
    int assumed = old;
    old = atomicCAS(ai, assumed, __float_as_int(val));
    if (old == assumed) break;
  }
}

// ---------------- weight prep: pack W_hi into mma B-fragment order ----------
// Per tap: u32 slot = ((wn*4+q)*2+quad)*128 + L*4 + r
//   n  = wn*32 + quad*16 + (r>>1)*8 + (L>>2)
//   kk = q*16 + (L&3)*2 + (r&1)*8
__global__ void wprep_kernel(const float* __restrict__ W1,
                             const float* __restrict__ W2,
                             const float* __restrict__ Wk){
  int gid = blockIdx.x*256 + threadIdx.x;
  if (gid >= 5*KN*2048) return;
  int slot = gid & 2047;
  int tk = gid >> 11;
  int l = tk/KN, k = tk - l*KN;
  const float* Ws = (l==0)? W1 : (l==1)? W2 : (Wk + (size_t)(l-2)*KN*CH*CH);
  int r    = slot & 3;
  int L    = (slot >> 2) & 31;
  int rest = slot >> 7;
  int quad = rest & 1;
  int q    = (rest >> 1) & 3;
  int wn   = rest >> 3;
  int n  = wn*32 + quad*16 + (r>>1)*8 + (L>>2);
  int kk = q*16 + (L&3)*2 + (r&1)*8;
  __half b0 = __float2half(Ws[k*CH*CH + kk*CH + n]);
  __half b1 = __float2half(Ws[k*CH*CH + (kk+1)*CH + n]);
  g_wswz[tk*2048 + slot] =
      (uint32_t)__half_as_ushort(b0) | ((uint32_t)__half_as_ushort(b1) << 16);
}

// ---------------- fp32 -> fp16 conversion of layer-0 input ------------------
__global__ void cvt_kernel(const float4* __restrict__ x,
                           __half2* __restrict__ ho){
  int i4 = blockIdx.x*256 + threadIdx.x;
  float4 v = x[i4];
  ho[2*i4]   = __halves2half2(__float2half(v.x), __float2half(v.y));
  ho[2*i4+1] = __halves2half2(__float2half(v.z), __float2half(v.w));
}

// ---------------- HMMA gathered conv -----------------------------------------
// Single-pass fp16: A_hi x W_hi. Pair tiling: 4 row-pairs (wm) x 2 col-halves (wn).
// A: smem 128 rows x 128B (hi only), TRIPLE-buffered (48KB), 1 pair-bar/tap.
// B: registers via LDG.128 (fragment-packed gmem, L2-hot), per-q double buffer.
#define NBR_OFF 49152
#define SM_DYN (49152 + 13824 + 1024)

__device__ __forceinline__ void ldgB(const uint4* __restrict__ bw,
                                     int k, int q, int wn, int L, uint32_t* B){
  const uint4* p = bw + (size_t)k*512 + (size_t)((wn*4 + q)*2)*32 + L;
  uint4 v0 = __ldg(p);
  uint4 v1 = __ldg(p + 32);
  B[0]=v0.x; B[1]=v0.y; B[2]=v0.z; B[3]=v0.w;
  B[4]=v1.x; B[5]=v1.y; B[6]=v1.z; B[7]=v1.w;
}

// A fill: 128 rows x 128B, thread t -> row t>>1, half (t&1) = 4 chunks of 16B
__device__ __forceinline__ void fillA(
    int k, int buf, int t, uint32_t sb, const int* __restrict__ snbr,
    const __half* __restrict__ hi)
{
  int r = (t>>6)*32 + ((t&63)>>1);   // pair-local rows
  int half = t & 1;
  int idx = snbr[r*KN + k];
  int sz = idx>=0 ? 16 : 0;
  int sidx = idx>=0 ? idx : 0;
  const char* asrc = (const char*)(hi + (size_t)sidx*CH);
  uint32_t rbase = sb + buf*16384 + (uint32_t)r*128;
  int xr = r & 7;
#pragma unroll
  for (int j=0;j<4;j++){
    int c = half*4 + j;
    int sw = c ^ xr;
    cp16z(rbase + sw*16, asrc + c*16, sz);
  }
}

__global__ void __launch_bounds__(256,2) conv_mma(
    const __half* __restrict__ hi,
    const int* __restrict__ nbr, const uint32_t* __restrict__ bswz,
    float* __restrict__ dst)
{
  extern __shared__ char smraw[];
  char* sm = (char*)(((uintptr_t)smraw + 1023) & ~(uintptr_t)1023);
  const uint32_t sb = smem_u32(sm);
  int* snbr = (int*)(sm + NBR_OFF);
  __shared__ float sred[128];
  const uint4* bw = (const uint4*)bswz;

  const int t   = threadIdx.x;
  const int L   = t & 31;
  const int wid = t >> 5;
  const int wm  = wid >> 1;
  const int wn  = wid & 1;
  const int row0 = blockIdx.x * 128;
  const int barid = 1 + wm;

  if (t < 128) sred[t] = 0.f;

  // prefetch neighbor indices (contiguous slice)
  {
    const int* src = nbr + (size_t)row0*KN;
#pragma unroll
    for (int i = 0; i < 14; i++){
      int o = t + i*256;
      if (o < 128*KN) snbr[o] = src[o];
    }
  }
  __syncthreads();

  float acc[2][4][4];
#pragma unroll
  for (int s=0;s<2;s++)
#pragma unroll
    for (int nb=0;nb<4;nb++)
#pragma unroll
      for (int i=0;i<4;i++) acc[s][nb][i]=0.f;

  // lane-constant ldmatrix address pieces (A only)
  const int arow_l  = ((L>>3)&1)*8 + (L&7);
  const int a_clane = (L>>4);
  const int arow    = wm*32 + arow_l;
  const int axor    = arow & 7;

  fillA(0, 0, t, sb, snbr, hi); CP_COMMIT();
  fillA(1, 1, t, sb, snbr, hi); CP_COMMIT();

  uint32_t Bb0[8], Bb1[8];
  ldgB(bw, 0, 0, wn, L, Bb0);

  int buf  = 0;
  int bufN = 2;

  for (int k = 0; k < KN; k++){
    CP_WAIT1();
    PAIR_BAR(barid);

    if (k+2 < KN) fillA(k+2, bufN, t, sb, snbr, hi);
    CP_COMMIT();

    const uint32_t Arow = sb + (uint32_t)buf*16384 + (uint32_t)arow*128;

#pragma unroll
    for (int q=0; q<4; q++){
      uint32_t* Bcur = (q&1) ? Bb1 : Bb0;
      uint32_t* Bnxt = (q&1) ? Bb0 : Bb1;
      if (q < 3) ldgB(bw, k, q+1, wn, L, Bnxt);
      else       ldgB(bw, (k+1<KN)?(k+1):k, 0, wn, L, Bnxt);

      uint32_t Ah0[4], Ah1[4];
      uint32_t ah = Arow + (uint32_t)(((q*2 + a_clane) ^ axor)*16);
      ldsm_x4(ah, Ah0);
      ldsm_x4(ah + 16*128, Ah1);

      hmma(acc[0][0], Ah0, Bcur[0], Bcur[1]);
      hmma(acc[0][1], Ah0, Bcur[2], Bcur[3]);
      hmma(acc[0][2], Ah0, Bcur[4], Bcur[5]);
      hmma(acc[0][3], Ah0, Bcur[6], Bcur[7]);
      hmma(acc[1][0], Ah1, Bcur[0], Bcur[1]);
      hmma(acc[1][1], Ah1, Bcur[2], Bcur[3]);
      hmma(acc[1][2], Ah1, Bcur[4], Bcur[5]);
      hmma(acc[1][3], Ah1, Bcur[6], Bcur[7]);
    }
    buf  = (buf  == 2) ? 0 : buf+1;
    bufN = (bufN == 2) ? 0 : bufN+1;
  }

  // ---- epilogue: stores + fused per-channel stats
#pragma unroll
  for (int s=0;s<2;s++){
    int r = row0 + wm*32 + s*16 + (L>>2);
#pragma unroll
    for (int nb=0;nb<4;nb++){
      int col = wn*32 + nb*8 + (L&3)*2;
      float* c = acc[s][nb];
      *(float2*)&dst[(size_t)r*CH + col]     = make_float2(c[0], c[1]);
      *(float2*)&dst[(size_t)(r+8)*CH + col] = make_float2(c[2], c[3]);
    }
  }
#pragma unroll
  for (int nb=0;nb<4;nb++){
    float sc0=0.f, sc1=0.f, qc0=0.f, qc1=0.f;
#pragma unroll
    for (int s=0;s<2;s++){
      float* c = acc[s][nb];
      sc0 += c[0]+c[2]; qc0 += c[0]*c[0]+c[2]*c[2];
      sc1 += c[1]+c[3]; qc1 += c[1]*c[1]+c[3]*c[3];
    }
#pragma unroll
    for (int m=4;m<32;m<<=1){
      sc0 += __shfl_xor_sync(0xFFFFFFFFu, sc0, m);
      sc1 += __shfl_xor_sync(0xFFFFFFFFu, sc1, m);
      qc0 += __shfl_xor_sync(0xFFFFFFFFu, qc0, m);
      qc1 += __shfl_xor_sync(0xFFFFFFFFu, qc1, m);
    }
    if (L < 4){
      int col = wn*32 + nb*8 + L*2;
      atomicAdd(&sred[col],    sc0); atomicAdd(&sred[col+1],    sc1);
      atomicAdd(&sred[64+col], qc0); atomicAdd(&sred[64+col+1], qc1);
    }
  }
  __syncthreads();
  if (t < 64){
    atomicAdd(&g_sum[t],   sred[t]);
    atomicAdd(&g_sumsq[t], sred[64+t]);
  }
}

// ---------------- stats clear ----------------------------------------------
__global__ void clear_stats_kernel(){
  int t = threadIdx.x; if (t < CH){ g_sum[t]=0.f; g_sumsq[t]=0.f; }
}

// ---------------- BN apply + emit fp32 and/or fp16 --------------------------
__global__ void bn2_kernel(const float* __restrict__ x, const float* __restrict__ gg,
                           const float* __restrict__ bb, int relu,
                           float* __restrict__ fout,
                           __half2* __restrict__ ho){
  __shared__ float sc[64], bi[64];
  int t = threadIdx.x;
  if (t < 64){
    float m = g_sum[t]*(1.f/NPTS);
    float v = g_sumsq[t]*(1.f/NPTS) - m*m;
    float s = rsqrtf(v + 1e-5f) * gg[t];
    sc[t] = s; bi[t] = bb[t] - m*s;
  }
  __syncthreads();
  int i4 = blockIdx.x*256 + t;
  float4 v = ((const float4*)x)[i4];
  int c = (i4 & 15)*4;
  v.x = v.x*sc[c]+bi[c];     v.y = v.y*sc[c+1]+bi[c+1];
  v.z = v.z*sc[c+2]+bi[c+2]; v.w = v.w*sc[c+3]+bi[c+3];
  if (relu){ v.x=fmaxf(v.x,0.f); v.y=fmaxf(v.y,0.f); v.z=fmaxf(v.z,0.f); v.w=fmaxf(v.w,0.f); }
  if (fout) ((float4*)fout)[i4] = v;
  if (ho){
    ho[2*i4]   = __halves2half2(__float2half(v.x), __float2half(v.y));
    ho[2*i4+1] = __halves2half2(__float2half(v.z), __float2half(v.w));
  }
}

// ---------------- segment sum/max over batches (B=2), 192 channels ---------
__global__ void clear_seg_kernel(){
  int t = threadIdx.x; if (t < NB*CAQ){ g_segsum[t]=0.f; g_segmax[t]=-FLT_MAX; }
}
__global__ void seg_kernel(const int* __restrict__ bidx){
  int j = threadIdx.x;
  const float* kxp = (j<64)? g_kx0 : ((j<128)? g_kx1 : g_kx2);
  int c = j & 63;
  int n0 = blockIdx.x*400, n1 = n0+400;
  float s0=0.f, s1=0.f, m0=-FLT_MAX, m1=-FLT_MAX;
  for (int n=n0;n<n1;n++){
    float v = kxp[n*CH + c];
    if (bidx[n]==0){ s0+=v; m0=fmaxf(m0,v); } else { s1+=v; m1=fmaxf(m1,v); }
  }
  atomicAdd(&g_segsum[j], s0);
  atomicAdd(&g_segsum[CAQ+j], s1);
  atomicMaxFloat(&g_segmax[j], m0);
  atomicMaxFloat(&g_segmax[CAQ+j], m1);
}

// ---------------- tiny FC + sigmoid attention ------------------------------
__global__ void fc_kernel(const int* __restrict__ bidx,
    const float* __restrict__ w1, const float* __restrict__ b1,
    const float* __restrict__ w2, const float* __restrict__ b2,
    const float* __restrict__ ksw)
{
  __shared__ float ha[NB][HID], hm[NB][HID];
  __shared__ int red[256];
  __shared__ int scnt[NB];
  int t = threadIdx.x;
  int c0 = 0;
  for (int n=t; n<NPTS; n+=256) c0 += (bidx[n]==0);
  red[t]=c0; __syncthreads();
  for (int s=128;s>0;s>>=1){ if (t<s) red[t]+=red[t+s]; __syncthreads(); }
  if (t==0){ scnt[0]=red[0]; scnt[1]=NPTS-red[0]; }
  __syncthreads();
  if (t<48){
    int which = t/24;
    int b  = (t/12)%2;
    int tt = t%12;
    float s = b1[tt];
    float inv = 1.f/(float)scnt[b];
    for (int j=0;j<CAQ;j++){
      float z = which ? g_segmax[b*CAQ+j] : g_segsum[b*CAQ+j]*inv;
      s += z * w1[j*HID+tt];
    }
    s = fmaxf(s,0.f);
    if (which) hm[b][tt]=s; else ha[b][tt]=s;
  }
  __syncthreads();
  for (int o=t; o<NB*CAQ; o+=256){
    int b=o/CAQ, j=o%CAQ;
    float sa=b2[j], sm=b2[j];
    for (int tt=0;tt<HID;tt++){ sa += ha[b][tt]*w2[tt*CAQ+j]; sm += hm[b][tt]*w2[tt*CAQ+j]; }
    float s = sa+sm;
    g_att[o] = 1.f/(1.f+expf(-s));
  }
  if (t<NXX) g_wsig[t] = 1.f/(1.f+expf(-ksw[t]));
}

// ---------------- fusion epilogue ------------------------------------------
__device__ __forceinline__ float kx_read(int sel, int off){
  return sel==0 ? g_kx0[off] : (sel==1 ? g_kx1[off] : g_kx2[off]);
}
__global__ void final_kernel(const float* __restrict__ feats,
                             const int* __restrict__ bidx,
                             float* __restrict__ out){
  int i = blockIdx.x*256 + threadIdx.x;
  int n = i >> 6, c = i & 63;
  int b = bidx[n];
  float acc = feats[i];
#pragma unroll
  for (int ii=0; ii<NXX; ii++){
    int j = 3*c + ii;
    int sel = j >> 6, col = j & 63;
    float xj  = kx_read(sel, n*CH + col);
    float kxi = kx_read(ii, i);
    acc += g_wsig[ii] * (kxi + xj * g_att[b*CAQ + j]);
  }
  out[i] = fmaxf(acc, 0.f);
}

// ---------------- launch ----------------------------------------------------
extern "C" void kernel_launch(void* const* d_in, const int* in_sizes, int n_in,
                              void* d_out, int out_size){
  (void)in_sizes; (void)n_in; (void)out_size;
  const float* feats=(const float*)d_in[0];
  const int*   bidx =(const int*)d_in[1];
  const int*   nbr  =(const int*)d_in[2];
  const float* W1 =(const float*)d_in[3];
  const float* g1 =(const float*)d_in[4];
  const float* b1 =(const float*)d_in[5];
  const float* W2 =(const float*)d_in[6];
  const float* g2 =(const float*)d_in[7];
  const float* b2 =(const float*)d_in[8];
  const float* Wk =(const float*)d_in[9];
  const float* gk =(const float*)d_in[10];
  const float* bk =(const float*)d_in[11];
  const float* fc1w=(const float*)d_in[12];
  const float* fc1b=(const float*)d_in[13];
  const float* fc2w=(const float*)d_in[14];
  const float* fc2b=(const float*)d_in[15];
  const float* ksw =(const float*)d_in[16];
  float* out=(float*)d_out;

  float *pConv,*pk0,*pk1,*pk2;
  __half2 *pHiA,*pHiB;
  uint32_t* pW;
  cudaGetSymbolAddress((void**)&pConv, g_conv);
  cudaGetSymbolAddress((void**)&pk0, g_kx0);
  cudaGetSymbolAddress((void**)&pk1, g_kx1);
  cudaGetSymbolAddress((void**)&pk2, g_kx2);
  cudaGetSymbolAddress((void**)&pHiA, g_hiA);
  cudaGetSymbolAddress((void**)&pHiB, g_hiB);
  cudaGetSymbolAddress((void**)&pW,  g_wswz);

  cudaFuncSetAttribute(conv_mma, cudaFuncAttributeMaxDynamicSharedMemorySize, SM_DYN);

  wprep_kernel<<<(5*KN*2048 + 255)/256, 256>>>(W1, W2, Wk);
  cvt_kernel<<<NPTS*CH/4/256, 256>>>((const float4*)feats, pHiA);

  struct Step {
    const __half *hi; const uint32_t* bw;
    const float *g, *b; int relu;
    float* fout; __half2 *ho;
  };
  Step steps[5] = {
    {(const __half*)pHiA, pW + 0*KN*2048, g1,      b1,      1, nullptr, pHiB},
    {(const __half*)pHiB, pW + 1*KN*2048, g2,      b2,      0, nullptr, pHiA},
    {(const __half*)pHiA, pW + 2*KN*2048, gk,      bk,      1, pk0,     pHiB},
    {(const __half*)pHiB, pW + 3*KN*2048, gk+CH,   bk+CH,   1, pk1,     pHiA},
    {(const __half*)pHiA, pW + 4*KN*2048, gk+2*CH, bk+2*CH, 1, pk2,     nullptr},
  };
  for (int s=0;s<5;s++){
    clear_stats_kernel<<<1,64>>>();
    conv_mma<<<NPTS/128, 256, SM_DYN>>>(steps[s].hi, nbr, steps[s].bw, pConv);
    bn2_kernel<<<NPTS*CH/4/256, 256>>>(pConv, steps[s].g, steps[s].b, steps[s].relu,
                                       steps[s].fout, steps[s].ho);
  }
  clear_seg_kernel<<<1, NB*CAQ>>>();
  seg_kernel<<<200, CAQ>>>(bidx);
  fc_kernel<<<1,256>>>(bidx, fc1w, fc1b, fc2w, fc2b, ksw);
  final_kernel<<<(NPTS*CH)/256, 256>>>(feats, bidx, out);
}